// round 2
// baseline (speedup 1.0000x reference)
#include <cuda_runtime.h>

// Problem constants
#define IH 16
#define IW 64
#define LSEQ 1024        // IH*IW
#define EE 256
#define BB 16
#define HH 8
#define DHH 32           // EE / HH
#define M_ROWS (BB*LSEQ) // 16384

// Scratch in __device__ globals (no allocation allowed)
__device__ float g_qkv[(size_t)BB * LSEQ * 3 * EE];   // 48 MB
__device__ float g_ctx[(size_t)BB * LSEQ * EE];       // 16 MB
__device__ float g_wf[EE * EE];                       // fused proj_w @ out_proj_w
__device__ float g_bf[EE];                            // fused proj_w @ out_proj_b

// ---------------------------------------------------------------------------
// Kernel: fuse the two output projections.
//   W_f[i][j] = sum_k proj_w[i][k] * out_proj_w[k][j]
//   b_f[i]    = sum_k proj_w[i][k] * out_proj_b[k]
// grid = 256 blocks (one per row i), 256 threads (one per col j)
// ---------------------------------------------------------------------------
__global__ void fuse_kernel(const float* __restrict__ wproj,
                            const float* __restrict__ wout,
                            const float* __restrict__ bout) {
    __shared__ float s_pw[EE];
    __shared__ float s_red[256];
    const int i = blockIdx.x;
    const int t = threadIdx.x;
    s_pw[t] = wproj[i * EE + t];
    __syncthreads();
    float acc = 0.f;
#pragma unroll 8
    for (int k = 0; k < EE; k++) acc += s_pw[k] * wout[k * EE + t];
    g_wf[i * EE + t] = acc;

    // fused bias via block reduce
    s_red[t] = s_pw[t] * bout[t];
    __syncthreads();
    for (int off = 128; off > 0; off >>= 1) {
        if (t < off) s_red[t] += s_red[t + off];
        __syncthreads();
    }
    if (t == 0) g_bf[i] = s_red[0];
}

// ---------------------------------------------------------------------------
// Shared SGEMM body: C[M,N] = A[M,K] @ B[N,K]^T + bias[N]
// BM=BN=128, BK=16, 256 threads, 8x8 micro-tile per thread.
// grid.x = N/128, grid.y = M/128
// ---------------------------------------------------------------------------
__device__ __forceinline__ void sgemm_bt_body(const float* __restrict__ A,
                                              const float* __restrict__ B,
                                              const float* __restrict__ bias,
                                              float* __restrict__ C,
                                              int N, int K) {
    __shared__ float As[16][128];
    __shared__ float Bs[16][128];
    const int tid = threadIdx.x;
    const int m0 = blockIdx.y * 128;
    const int n0 = blockIdx.x * 128;
    const int tm = (tid >> 4) * 8;   // 16 row-groups
    const int tn = (tid & 15) * 8;   // 16 col-groups

    float acc[8][8];
#pragma unroll
    for (int i = 0; i < 8; i++)
#pragma unroll
        for (int j = 0; j < 8; j++) acc[i][j] = 0.f;

    for (int k0 = 0; k0 < K; k0 += 16) {
        // load tiles: 2048 elems each, 8 per thread
#pragma unroll
        for (int e = tid; e < 128 * 16; e += 256) {
            const int m = e >> 4;
            const int k = e & 15;
            As[k][m] = A[(size_t)(m0 + m) * K + k0 + k];
            Bs[k][m] = B[(size_t)(n0 + m) * K + k0 + k];
        }
        __syncthreads();
#pragma unroll
        for (int k = 0; k < 16; k++) {
            float a[8], b[8];
#pragma unroll
            for (int i = 0; i < 8; i++) a[i] = As[k][tm + i];
#pragma unroll
            for (int j = 0; j < 8; j++) b[j] = Bs[k][tn + j];
#pragma unroll
            for (int i = 0; i < 8; i++)
#pragma unroll
                for (int j = 0; j < 8; j++) acc[i][j] += a[i] * b[j];
        }
        __syncthreads();
    }

#pragma unroll
    for (int i = 0; i < 8; i++) {
        float* crow = C + (size_t)(m0 + tm + i) * N + n0 + tn;
#pragma unroll
        for (int j = 0; j < 8; j++) {
            crow[j] = acc[i][j] + bias[n0 + tn + j];
        }
    }
}

// QKV GEMM: x[16384,256] @ in_proj_w[768,256]^T + b -> g_qkv
__global__ void qkv_gemm_kernel(const float* __restrict__ x,
                                const float* __restrict__ w,
                                const float* __restrict__ bias) {
    sgemm_bt_body(x, w, bias, g_qkv, 3 * EE, EE);
}

// Output GEMM: g_ctx[16384,256] @ g_wf[256,256]^T + g_bf -> out
__global__ void out_gemm_kernel(float* __restrict__ out) {
    sgemm_bt_body(g_ctx, g_wf, g_bf, out, EE, EE);
}

// ---------------------------------------------------------------------------
// Local-window attention. One block per (b, h, image_row r): 64 queries.
// Loads K/V halo rows [r-3, r+3] (<=448 keys x 32 dims) into smem, padded to
// stride 33 for conflict-free access. One warp handles 8 queries serially;
// within a query, lanes split keys for scores/softmax, then lanes = dims for PV.
// ---------------------------------------------------------------------------
#define ATTN_SMEM_FLOATS (448 * 33 * 2 + 64 * 32 + 8 * 80)
#define ATTN_SMEM_BYTES (ATTN_SMEM_FLOATS * 4)

__global__ void attn_kernel() {
    extern __shared__ float smem[];
    float* sK = smem;                    // [448][33]
    float* sV = sK + 448 * 33;           // [448][33]
    float* sQ = sV + 448 * 33;           // [64][32]
    float* sW = sQ + 64 * 32;            // [8 warps][80]

    const int bid = blockIdx.x;          // b*128 + h*16 + r
    const int r = bid & 15;
    const int h = (bid >> 4) & 7;
    const int b = bid >> 7;
    const int tid = threadIdx.x;

    const int rlo = max(0, r - 3);
    const int rhi = min(IH - 1, r + 3);
    const int nrows = rhi - rlo + 1;
    const int nkeysKV = nrows * IW;

    const float* __restrict__ qkvb = g_qkv + (size_t)b * LSEQ * (3 * EE);

    // cooperative load of K and V halo
    for (int e = tid; e < nkeysKV * 32; e += 256) {
        const int key = e >> 5;
        const int d = e & 31;
        const int l = (rlo + (key >> 6)) * IW + (key & 63);
        const float* src = qkvb + (size_t)l * (3 * EE) + h * DHH + d;
        sK[key * 33 + d] = src[EE];
        sV[key * 33 + d] = src[2 * EE];
    }
    // load Q for the 64 queries of this row
    for (int e = tid; e < 64 * 32; e += 256) {
        const int c = e >> 5;
        const int d = e & 31;
        sQ[e] = qkvb[(size_t)(r * IW + c) * (3 * EE) + h * DHH + d];
    }
    __syncthreads();

    const int w = tid >> 5;
    const int lane = tid & 31;
    const float scale = 0.17677669529663687f;  // 1/sqrt(32)
    float* ctx_out = g_ctx + ((size_t)b * LSEQ + r * IW) * EE + h * DHH;
    float* myW = sW + w * 80;

    for (int qi = 0; qi < 8; qi++) {
        const int c = w * 8 + qi;
        const int clo = max(0, c - 5);
        const int chi = min(IW - 1, c + 5);
        const int nc = chi - clo + 1;
        const int nk = nrows * nc;     // <= 77

        // scores for this lane's keys (<=3)
        float sv[3];
        int cnt = 0;
        const float* qp = sQ + c * 32;
        for (int i = lane; i < nk; i += 32) {
            const int kr = i / nc;
            const int kc = clo + (i - kr * nc);
            const float* kp = sK + (kr * IW + kc) * 33;
            float dot = 0.f;
#pragma unroll
            for (int d = 0; d < 32; d++) dot += qp[d] * kp[d];
            sv[cnt++] = dot * scale;
        }
        // warp softmax
        float m = -1e30f;
        for (int j = 0; j < cnt; j++) m = fmaxf(m, sv[j]);
#pragma unroll
        for (int off = 16; off; off >>= 1) m = fmaxf(m, __shfl_xor_sync(0xffffffffu, m, off));
        float ssum = 0.f;
        for (int j = 0; j < cnt; j++) { sv[j] = expf(sv[j] - m); ssum += sv[j]; }
#pragma unroll
        for (int off = 16; off; off >>= 1) ssum += __shfl_xor_sync(0xffffffffu, ssum, off);
        const float inv = 1.f / ssum;
        cnt = 0;
        for (int i = lane; i < nk; i += 32) myW[i] = sv[cnt++] * inv;
        __syncwarp();

        // PV: lane == output dim
        float acc = 0.f;
        int i = 0;
        for (int kr = 0; kr < nrows; kr++) {
            const float* vp = sV + (kr * IW + clo) * 33 + lane;
            for (int kc = 0; kc < nc; kc++) { acc += myW[i] * vp[kc * 33]; i++; }
        }
        ctx_out[(size_t)c * EE + lane] = acc;
        __syncwarp();
    }
}

// ---------------------------------------------------------------------------
extern "C" void kernel_launch(void* const* d_in, const int* in_sizes, int n_in,
                              void* d_out, int out_size) {
    const float* patch_embed = (const float*)d_in[0];  // [16,1024,256]
    const float* in_proj_w   = (const float*)d_in[1];  // [768,256]
    const float* in_proj_b   = (const float*)d_in[2];  // [768]
    const float* out_proj_w  = (const float*)d_in[3];  // [256,256]
    const float* out_proj_b  = (const float*)d_in[4];  // [256]
    const float* proj_w      = (const float*)d_in[5];  // [256,256]
    float* out = (float*)d_out;                        // [16,1024,256]

    // opt-in to >48KB dynamic smem for attention (idempotent, capture-safe)
    static bool attr_set = false;
    if (!attr_set) {
        cudaFuncSetAttribute(attn_kernel, cudaFuncAttributeMaxDynamicSharedMemorySize,
                             ATTN_SMEM_BYTES);
        attr_set = true;
    }

    // fused output-projection weights (independent of x; cheap)
    fuse_kernel<<<EE, 256>>>(proj_w, out_proj_w, out_proj_b);
    // QKV projection
    qkv_gemm_kernel<<<dim3((3 * EE) / 128, M_ROWS / 128), 256>>>(patch_embed, in_proj_w, in_proj_b);
    // local attention
    attn_kernel<<<BB * HH * IH, 256, ATTN_SMEM_BYTES>>>();
    // fused output projection straight into d_out
    out_gemm_kernel<<<dim3(EE / 128, M_ROWS / 128), 256>>>(out);
}

// round 9
// speedup vs baseline: 1.7314x; 1.7314x over previous
#include <cuda_runtime.h>
#include <cuda_bf16.h>
#include <cstdint>

// Problem constants
#define IH 16
#define IW 64
#define LSEQ 1024        // IH*IW
#define EE 256
#define BB 16
#define HH 8
#define DHH 32           // EE / HH
#define M_ROWS (BB*LSEQ) // 16384

// ---------------------------------------------------------------------------
// Base-ISA helpers (sm_80-era: work on plain sm_103 target; NO tcgen05)
// ---------------------------------------------------------------------------
__device__ __forceinline__ uint32_t smem_u32(const void* p) {
    uint32_t a;
    asm("{ .reg .u64 t; cvta.to.shared.u64 t, %1; cvt.u32.u64 %0, t; }" : "=r"(a) : "l"(p));
    return a;
}
__device__ __forceinline__ void cp_async16(uint32_t saddr, const void* g) {
    asm volatile("cp.async.cg.shared.global [%0], [%1], 16;" :: "r"(saddr), "l"(g));
}
#define CP_COMMIT() asm volatile("cp.async.commit_group;" ::: "memory")

#define LDSM_X4(r0, r1, r2, r3, addr) \
    asm volatile("ldmatrix.sync.aligned.m8n8.x4.shared.b16 {%0,%1,%2,%3}, [%4];" \
        : "=r"(r0), "=r"(r1), "=r"(r2), "=r"(r3) : "r"(addr))

__device__ __forceinline__ void mma16816(float* d, const uint32_t* a, const uint32_t* b) {
    asm volatile(
        "mma.sync.aligned.m16n8k16.row.col.f32.bf16.bf16.f32 "
        "{%0,%1,%2,%3},{%4,%5,%6,%7},{%8,%9},{%0,%1,%2,%3};"
        : "+f"(d[0]), "+f"(d[1]), "+f"(d[2]), "+f"(d[3])
        : "r"(a[0]), "r"(a[1]), "r"(a[2]), "r"(a[3]), "r"(b[0]), "r"(b[1]));
}

// ---------------------------------------------------------------------------
// Scratch (__device__ globals; no allocation allowed)
// ---------------------------------------------------------------------------
__device__ float          g_qkv[(size_t)M_ROWS * 3 * EE];   // fp32 for attention
__device__ __nv_bfloat16  g_x_hi[(size_t)M_ROWS * EE];
__device__ __nv_bfloat16  g_x_lo[(size_t)M_ROWS * EE];
__device__ __nv_bfloat16  g_wq_hi[3 * EE * EE];
__device__ __nv_bfloat16  g_wq_lo[3 * EE * EE];
__device__ __nv_bfloat16  g_wf_hi[EE * EE];
__device__ __nv_bfloat16  g_wf_lo[EE * EE];
__device__ float          g_bf[EE];
__device__ __nv_bfloat16  g_ctx_hi[(size_t)M_ROWS * EE];
__device__ __nv_bfloat16  g_ctx_lo[(size_t)M_ROWS * EE];

// ---------------------------------------------------------------------------
// fp32 -> bf16 hi/lo split (elementwise, vectorized x4)
// ---------------------------------------------------------------------------
__global__ void split_kernel(const float* __restrict__ src,
                             __nv_bfloat16* __restrict__ hi,
                             __nv_bfloat16* __restrict__ lo, int n4) {
    int i = blockIdx.x * blockDim.x + threadIdx.x;
    if (i >= n4) return;
    float4 x = reinterpret_cast<const float4*>(src)[i];
    __nv_bfloat16 h0 = __float2bfloat16(x.x);
    __nv_bfloat16 h1 = __float2bfloat16(x.y);
    __nv_bfloat16 h2 = __float2bfloat16(x.z);
    __nv_bfloat16 h3 = __float2bfloat16(x.w);
    __nv_bfloat162 ha; ha.x = h0; ha.y = h1;
    __nv_bfloat162 hb; hb.x = h2; hb.y = h3;
    reinterpret_cast<__nv_bfloat162*>(hi)[2 * i]     = ha;
    reinterpret_cast<__nv_bfloat162*>(hi)[2 * i + 1] = hb;
    __nv_bfloat162 la, lb;
    la.x = __float2bfloat16(x.x - __bfloat162float(h0));
    la.y = __float2bfloat16(x.y - __bfloat162float(h1));
    lb.x = __float2bfloat16(x.z - __bfloat162float(h2));
    lb.y = __float2bfloat16(x.w - __bfloat162float(h3));
    reinterpret_cast<__nv_bfloat162*>(lo)[2 * i]     = la;
    reinterpret_cast<__nv_bfloat162*>(lo)[2 * i + 1] = lb;
}

// ---------------------------------------------------------------------------
// Fuse output projections: W_f = proj_w @ out_proj_w (emit bf16 hi/lo),
// b_f = proj_w @ out_proj_b (fp32).
// ---------------------------------------------------------------------------
__global__ void fuse_kernel(const float* __restrict__ wproj,
                            const float* __restrict__ wout,
                            const float* __restrict__ bout) {
    __shared__ float s_pw[EE];
    __shared__ float s_red[256];
    const int i = blockIdx.x;
    const int t = threadIdx.x;
    s_pw[t] = wproj[i * EE + t];
    __syncthreads();
    float acc = 0.f;
#pragma unroll 8
    for (int k = 0; k < EE; k++) acc += s_pw[k] * wout[k * EE + t];
    __nv_bfloat16 hv = __float2bfloat16(acc);
    g_wf_hi[i * EE + t] = hv;
    g_wf_lo[i * EE + t] = __float2bfloat16(acc - __bfloat162float(hv));

    s_red[t] = s_pw[t] * bout[t];
    __syncthreads();
    for (int off = 128; off > 0; off >>= 1) {
        if (t < off) s_red[t] += s_red[t + off];
        __syncthreads();
    }
    if (t == 0) g_bf[i] = s_red[0];
}

// ---------------------------------------------------------------------------
// HMMA split-bf16 GEMM: C[M, Ntot] = A[M,256] @ W[Ntot,256]^T + bias.
// A,W as bf16 (hi, lo); 3 mma passes (hh + hl + lh) into fp32 accumulators.
// CTA 128x128, K chunks of 64, double-buffered cp.async, xor-swizzled smem
// for conflict-free ldmatrix. 8 warps in 4(M)x2(N); warp tile 32x64.
// Stage layout: Ahi | Alo | Bhi | Blo, each 128 rows x 64 bf16 (128B rows).
// ---------------------------------------------------------------------------
#define STAGE_BYTES 65536
#define GEMM_SMEM_BYTES (2 * STAGE_BYTES)

__device__ __forceinline__ void load_stage(uint32_t sbase, int stage,
                                           const __nv_bfloat16* __restrict__ Ahi,
                                           const __nv_bfloat16* __restrict__ Alo,
                                           const __nv_bfloat16* __restrict__ Bhi,
                                           const __nv_bfloat16* __restrict__ Blo,
                                           int m0, int n0, int kc, int tid) {
    const uint32_t dst = sbase + stage * STAGE_BYTES;
    const __nv_bfloat16* __restrict__ srcs[4] = {
        Ahi + (size_t)m0 * 256, Alo + (size_t)m0 * 256,
        Bhi + (size_t)n0 * 256, Blo + (size_t)n0 * 256 };
#pragma unroll
    for (int arr = 0; arr < 4; arr++) {
        const __nv_bfloat16* __restrict__ s = srcs[arr];
#pragma unroll
        for (int c = 0; c < 4; c++) {             // 1024 16B-chunks / 256 thr
            const int idx = c * 256 + tid;
            const int row = idx >> 3;
            const int k16 = idx & 7;
            const uint32_t soff = (uint32_t)(row << 7) + (uint32_t)((k16 ^ (row & 7)) << 4);
            cp_async16(dst + arr * 16384 + soff,
                       s + (size_t)row * 256 + kc * 64 + k16 * 8);
        }
    }
    CP_COMMIT();
}

__global__ __launch_bounds__(256, 1)
void tc_gemm_kernel(const __nv_bfloat16* __restrict__ Ahi, const __nv_bfloat16* __restrict__ Alo,
                    const __nv_bfloat16* __restrict__ Bhi, const __nv_bfloat16* __restrict__ Blo,
                    const float* __restrict__ bias, float* __restrict__ C, int Ntot) {
    extern __shared__ char dsm[];
    const uint32_t sbase = smem_u32(dsm);

    const int tid = threadIdx.x;
    const int wid = tid >> 5;
    const int lane = tid & 31;
    const int n0 = blockIdx.x * 128;
    const int m0 = blockIdx.y * 128;
    const int wm = wid >> 1;     // 0..3 -> M offset wm*32
    const int wn = wid & 1;      // 0..1 -> N offset wn*64

    float acc[2][8][4];
#pragma unroll
    for (int mt = 0; mt < 2; mt++)
#pragma unroll
        for (int nt = 0; nt < 8; nt++)
#pragma unroll
            for (int e = 0; e < 4; e++) acc[mt][nt][e] = 0.f;

    load_stage(sbase, 0, Ahi, Alo, Bhi, Blo, m0, n0, 0, tid);

    const int q = lane >> 3;     // ldmatrix quad
    const int r = lane & 7;

    for (int kc = 0; kc < 4; kc++) {
        if (kc < 3) {
            load_stage(sbase, (kc + 1) & 1, Ahi, Alo, Bhi, Blo, m0, n0, kc + 1, tid);
            asm volatile("cp.async.wait_group 1;" ::: "memory");
        } else {
            asm volatile("cp.async.wait_group 0;" ::: "memory");
        }
        __syncthreads();

        const uint32_t st = sbase + (kc & 1) * STAGE_BYTES;
#pragma unroll
        for (int s = 0; s < 4; s++) {
            // ---- A fragments (hi & lo), 2 m16 tiles
            uint32_t aHi[2][4], aLo[2][4];
#pragma unroll
            for (int mt = 0; mt < 2; mt++) {
                const int arow = wm * 32 + mt * 16 + ((q & 1) << 3) + r;
                const int ac = 2 * s + (q >> 1);
                const uint32_t ad = st + (uint32_t)(arow << 7) + (uint32_t)((ac ^ (arow & 7)) << 4);
                LDSM_X4(aHi[mt][0], aHi[mt][1], aHi[mt][2], aHi[mt][3], ad);
                LDSM_X4(aLo[mt][0], aLo[mt][1], aLo[mt][2], aLo[mt][3], ad + 16384);
            }
            // ---- B fragments (hi & lo), 8 n8 tiles as 4 pairs
            uint32_t bHi[8][2], bLo[8][2];
#pragma unroll
            for (int p = 0; p < 4; p++) {
                const int brow = wn * 64 + p * 16 + ((q >> 1) << 3) + r;
                const int bc = 2 * s + (q & 1);
                const uint32_t bd = st + 32768u + (uint32_t)(brow << 7) + (uint32_t)((bc ^ (brow & 7)) << 4);
                uint32_t t0, t1, t2, t3;
                LDSM_X4(t0, t1, t2, t3, bd);
                bHi[2 * p][0] = t0; bHi[2 * p][1] = t1;
                bHi[2 * p + 1][0] = t2; bHi[2 * p + 1][1] = t3;
                LDSM_X4(t0, t1, t2, t3, bd + 16384);
                bLo[2 * p][0] = t0; bLo[2 * p][1] = t1;
                bLo[2 * p + 1][0] = t2; bLo[2 * p + 1][1] = t3;
            }
            // ---- 3-pass split mma
#pragma unroll
            for (int mt = 0; mt < 2; mt++)
#pragma unroll
                for (int nt = 0; nt < 8; nt++) {
                    mma16816(acc[mt][nt], aHi[mt], bHi[nt]);
                    mma16816(acc[mt][nt], aHi[mt], bLo[nt]);
                    mma16816(acc[mt][nt], aLo[mt], bHi[nt]);
                }
        }
        __syncthreads();
    }

    // ---- epilogue: bias + fp32 store (float2 per fragment row)
    const int r_base = m0 + wm * 32 + (lane >> 2);
    const int c_base = n0 + wn * 64 + (lane & 3) * 2;
    float2 bv[8];
#pragma unroll
    for (int nt = 0; nt < 8; nt++)
        bv[nt] = *reinterpret_cast<const float2*>(bias + c_base + nt * 8);
#pragma unroll
    for (int mt = 0; mt < 2; mt++) {
        const int rw = r_base + mt * 16;
#pragma unroll
        for (int nt = 0; nt < 8; nt++) {
            float2 v0, v1;
            v0.x = acc[mt][nt][0] + bv[nt].x;
            v0.y = acc[mt][nt][1] + bv[nt].y;
            v1.x = acc[mt][nt][2] + bv[nt].x;
            v1.y = acc[mt][nt][3] + bv[nt].y;
            *reinterpret_cast<float2*>(C + (size_t)rw * Ntot + c_base + nt * 8) = v0;
            *reinterpret_cast<float2*>(C + (size_t)(rw + 8) * Ntot + c_base + nt * 8) = v1;
        }
    }
}

// ---------------------------------------------------------------------------
// Local-window attention. One block per (b, h, image_row r): 64 queries.
// K/V halo rows [r-3, r+3] in smem (stride 33, conflict-free). Q hoisted to
// registers per query (broadcast LDS once). Outputs bf16 hi/lo ctx.
// ---------------------------------------------------------------------------
#define ATTN_SMEM_FLOATS (448 * 33 * 2 + 64 * 32 + 8 * 80)
#define ATTN_SMEM_BYTES (ATTN_SMEM_FLOATS * 4)

__global__ void attn_kernel() {
    extern __shared__ float smem[];
    float* sK = smem;                    // [448][33]
    float* sV = sK + 448 * 33;           // [448][33]
    float* sQ = sV + 448 * 33;           // [64][32]
    float* sW = sQ + 64 * 32;            // [8 warps][80]

    const int bid = blockIdx.x;          // b*128 + h*16 + r
    const int rr = bid & 15;
    const int hh = (bid >> 4) & 7;
    const int b = bid >> 7;
    const int tid = threadIdx.x;

    const int rlo = max(0, rr - 3);
    const int rhi = min(IH - 1, rr + 3);
    const int nrows = rhi - rlo + 1;
    const int nkeysKV = nrows * IW;

    const float* __restrict__ qkvb = g_qkv + (size_t)b * LSEQ * (3 * EE);

    for (int e = tid; e < nkeysKV * 32; e += 256) {
        const int key = e >> 5;
        const int d = e & 31;
        const int l = (rlo + (key >> 6)) * IW + (key & 63);
        const float* src = qkvb + (size_t)l * (3 * EE) + hh * DHH + d;
        sK[key * 33 + d] = src[EE];
        sV[key * 33 + d] = src[2 * EE];
    }
    for (int e = tid; e < 64 * 32; e += 256) {
        sQ[e] = qkvb[(size_t)(rr * IW + (e >> 5)) * (3 * EE) + hh * DHH + (e & 31)];
    }
    __syncthreads();

    const int w = tid >> 5;
    const int lane = tid & 31;
    const float scale = 0.17677669529663687f;  // 1/sqrt(32)
    const size_t ctx_base = ((size_t)b * LSEQ + rr * IW) * EE + hh * DHH + lane;
    float* myW = sW + w * 80;

    for (int qi = 0; qi < 8; qi++) {
        const int c = w * 8 + qi;
        const int clo = max(0, c - 5);
        const int chi = min(IW - 1, c + 5);
        const int nc = chi - clo + 1;
        const int nk = nrows * nc;     // <= 77

        // hoist q into registers (broadcast LDS, once)
        float qreg[32];
        {
            const float* qp = sQ + c * 32;
#pragma unroll
            for (int d = 0; d < 32; d++) qreg[d] = qp[d];
        }

        float svv[3];
        int cnt = 0;
        for (int i = lane; i < nk; i += 32) {
            const int kr = i / nc;
            const int kcc = clo + (i - kr * nc);
            const float* kp = sK + (kr * IW + kcc) * 33;
            float dot = 0.f;
#pragma unroll
            for (int d = 0; d < 32; d++) dot += qreg[d] * kp[d];
            svv[cnt++] = dot * scale;
        }
        float m = -1e30f;
        for (int j = 0; j < cnt; j++) m = fmaxf(m, svv[j]);
#pragma unroll
        for (int off = 16; off; off >>= 1) m = fmaxf(m, __shfl_xor_sync(0xffffffffu, m, off));
        float ssum = 0.f;
        for (int j = 0; j < cnt; j++) { svv[j] = expf(svv[j] - m); ssum += svv[j]; }
#pragma unroll
        for (int off = 16; off; off >>= 1) ssum += __shfl_xor_sync(0xffffffffu, ssum, off);
        const float inv = 1.f / ssum;
        cnt = 0;
        for (int i = lane; i < nk; i += 32) myW[i] = svv[cnt++] * inv;
        __syncwarp();

        float acc = 0.f;
        int i = 0;
        for (int kr = 0; kr < nrows; kr++) {
            const float* vp = sV + (kr * IW + clo) * 33 + lane;
            for (int kcc = 0; kcc < nc; kcc++) { acc += myW[i] * vp[kcc * 33]; i++; }
        }
        const size_t oi = ctx_base + (size_t)c * EE;
        __nv_bfloat16 hv = __float2bfloat16(acc);
        g_ctx_hi[oi] = hv;
        g_ctx_lo[oi] = __float2bfloat16(acc - __bfloat162float(hv));
        __syncwarp();
    }
}

// ---------------------------------------------------------------------------
extern "C" void kernel_launch(void* const* d_in, const int* in_sizes, int n_in,
                              void* d_out, int out_size) {
    const float* patch_embed = (const float*)d_in[0];  // [16,1024,256]
    const float* in_proj_w   = (const float*)d_in[1];  // [768,256]
    const float* in_proj_b   = (const float*)d_in[2];  // [768]
    const float* out_proj_w  = (const float*)d_in[3];  // [256,256]
    const float* out_proj_b  = (const float*)d_in[4];  // [256]
    const float* proj_w      = (const float*)d_in[5];  // [256,256]
    float* out = (float*)d_out;                        // [16,1024,256]

    static bool init_done = false;
    static void *p_xhi, *p_xlo, *p_wqhi, *p_wqlo, *p_wfhi, *p_wflo, *p_bf, *p_chi, *p_clo, *p_qkv;
    if (!init_done) {
        cudaFuncSetAttribute(attn_kernel, cudaFuncAttributeMaxDynamicSharedMemorySize, ATTN_SMEM_BYTES);
        cudaFuncSetAttribute(tc_gemm_kernel, cudaFuncAttributeMaxDynamicSharedMemorySize, GEMM_SMEM_BYTES);
        cudaGetSymbolAddress(&p_xhi,  g_x_hi);
        cudaGetSymbolAddress(&p_xlo,  g_x_lo);
        cudaGetSymbolAddress(&p_wqhi, g_wq_hi);
        cudaGetSymbolAddress(&p_wqlo, g_wq_lo);
        cudaGetSymbolAddress(&p_wfhi, g_wf_hi);
        cudaGetSymbolAddress(&p_wflo, g_wf_lo);
        cudaGetSymbolAddress(&p_bf,   g_bf);
        cudaGetSymbolAddress(&p_chi,  g_ctx_hi);
        cudaGetSymbolAddress(&p_clo,  g_ctx_lo);
        cudaGetSymbolAddress(&p_qkv,  g_qkv);
        init_done = true;
    }

    // bf16 hi/lo splits of activations and qkv weights
    split_kernel<<<(M_ROWS * EE / 4 + 255) / 256, 256>>>(
        patch_embed, (__nv_bfloat16*)p_xhi, (__nv_bfloat16*)p_xlo, M_ROWS * EE / 4);
    split_kernel<<<(3 * EE * EE / 4 + 255) / 256, 256>>>(
        in_proj_w, (__nv_bfloat16*)p_wqhi, (__nv_bfloat16*)p_wqlo, 3 * EE * EE / 4);
    // fused output projection weights (hi/lo) + fused bias
    fuse_kernel<<<EE, 256>>>(proj_w, out_proj_w, out_proj_b);
    // QKV projection on tensor cores (HMMA) -> fp32 g_qkv
    tc_gemm_kernel<<<dim3(6, M_ROWS / 128), 256, GEMM_SMEM_BYTES>>>(
        (const __nv_bfloat16*)p_xhi, (const __nv_bfloat16*)p_xlo,
        (const __nv_bfloat16*)p_wqhi, (const __nv_bfloat16*)p_wqlo,
        in_proj_b, (float*)p_qkv, 3 * EE);
    // local attention -> bf16 hi/lo ctx
    attn_kernel<<<BB * HH * IH, 256, ATTN_SMEM_BYTES>>>();
    // fused output projection on tensor cores straight into d_out
    tc_gemm_kernel<<<dim3(2, M_ROWS / 128), 256, GEMM_SMEM_BYTES>>>(
        (const __nv_bfloat16*)p_chi, (const __nv_bfloat16*)p_clo,
        (const __nv_bfloat16*)p_wfhi, (const __nv_bfloat16*)p_wflo,
        (const float*)p_bf, out, EE);
}

// round 10
// speedup vs baseline: 2.8742x; 1.6601x over previous
#include <cuda_runtime.h>
#include <cuda_bf16.h>
#include <cstdint>

// Problem constants
#define IH 16
#define IW 64
#define LSEQ 1024        // IH*IW
#define EE 256
#define BB 16
#define HH 8
#define DHH 32           // EE / HH
#define M_ROWS (BB*LSEQ) // 16384

// ---------------------------------------------------------------------------
// Base-ISA helpers (sm_80-era: work on plain sm_103 target; NO tcgen05)
// ---------------------------------------------------------------------------
__device__ __forceinline__ uint32_t smem_u32(const void* p) {
    uint32_t a;
    asm("{ .reg .u64 t; cvta.to.shared.u64 t, %1; cvt.u32.u64 %0, t; }" : "=r"(a) : "l"(p));
    return a;
}
__device__ __forceinline__ void cp_async16(uint32_t saddr, const void* g) {
    asm volatile("cp.async.cg.shared.global [%0], [%1], 16;" :: "r"(saddr), "l"(g));
}
#define CP_COMMIT() asm volatile("cp.async.commit_group;" ::: "memory")

#define LDSM_X4(r0, r1, r2, r3, addr) \
    asm volatile("ldmatrix.sync.aligned.m8n8.x4.shared.b16 {%0,%1,%2,%3}, [%4];" \
        : "=r"(r0), "=r"(r1), "=r"(r2), "=r"(r3) : "r"(addr))

__device__ __forceinline__ void mma16816(float* d, const uint32_t* a, const uint32_t* b) {
    asm volatile(
        "mma.sync.aligned.m16n8k16.row.col.f32.bf16.bf16.f32 "
        "{%0,%1,%2,%3},{%4,%5,%6,%7},{%8,%9},{%0,%1,%2,%3};"
        : "+f"(d[0]), "+f"(d[1]), "+f"(d[2]), "+f"(d[3])
        : "r"(a[0]), "r"(a[1]), "r"(a[2]), "r"(a[3]), "r"(b[0]), "r"(b[1]));
}

// ---------------------------------------------------------------------------
// Scratch (__device__ globals; no allocation allowed)
// ---------------------------------------------------------------------------
__device__ float          g_qkv[(size_t)M_ROWS * 3 * EE];   // fp32 for attention
__device__ __nv_bfloat16  g_x_hi[(size_t)M_ROWS * EE];
__device__ __nv_bfloat16  g_x_lo[(size_t)M_ROWS * EE];
__device__ __nv_bfloat16  g_wq_hi[3 * EE * EE];
__device__ __nv_bfloat16  g_wq_lo[3 * EE * EE];
__device__ __nv_bfloat16  g_wf_hi[EE * EE];
__device__ __nv_bfloat16  g_wf_lo[EE * EE];
__device__ float          g_bf[EE];
__device__ __nv_bfloat16  g_ctx_hi[(size_t)M_ROWS * EE];
__device__ __nv_bfloat16  g_ctx_lo[(size_t)M_ROWS * EE];

// ---------------------------------------------------------------------------
// fp32 -> bf16 hi/lo split (elementwise, vectorized x4)
// ---------------------------------------------------------------------------
__global__ void split_kernel(const float* __restrict__ src,
                             __nv_bfloat16* __restrict__ hi,
                             __nv_bfloat16* __restrict__ lo, int n4) {
    int i = blockIdx.x * blockDim.x + threadIdx.x;
    if (i >= n4) return;
    float4 x = reinterpret_cast<const float4*>(src)[i];
    __nv_bfloat16 h0 = __float2bfloat16(x.x);
    __nv_bfloat16 h1 = __float2bfloat16(x.y);
    __nv_bfloat16 h2 = __float2bfloat16(x.z);
    __nv_bfloat16 h3 = __float2bfloat16(x.w);
    __nv_bfloat162 ha; ha.x = h0; ha.y = h1;
    __nv_bfloat162 hb; hb.x = h2; hb.y = h3;
    reinterpret_cast<__nv_bfloat162*>(hi)[2 * i]     = ha;
    reinterpret_cast<__nv_bfloat162*>(hi)[2 * i + 1] = hb;
    __nv_bfloat162 la, lb;
    la.x = __float2bfloat16(x.x - __bfloat162float(h0));
    la.y = __float2bfloat16(x.y - __bfloat162float(h1));
    lb.x = __float2bfloat16(x.z - __bfloat162float(h2));
    lb.y = __float2bfloat16(x.w - __bfloat162float(h3));
    reinterpret_cast<__nv_bfloat162*>(lo)[2 * i]     = la;
    reinterpret_cast<__nv_bfloat162*>(lo)[2 * i + 1] = lb;
}

// ---------------------------------------------------------------------------
// Fuse output projections: W_f = proj_w @ out_proj_w (emit bf16 hi/lo),
// b_f = proj_w @ out_proj_b (fp32).
// ---------------------------------------------------------------------------
__global__ void fuse_kernel(const float* __restrict__ wproj,
                            const float* __restrict__ wout,
                            const float* __restrict__ bout) {
    __shared__ float s_pw[EE];
    __shared__ float s_red[256];
    const int i = blockIdx.x;
    const int t = threadIdx.x;
    s_pw[t] = wproj[i * EE + t];
    __syncthreads();
    float acc = 0.f;
#pragma unroll 8
    for (int k = 0; k < EE; k++) acc += s_pw[k] * wout[k * EE + t];
    __nv_bfloat16 hv = __float2bfloat16(acc);
    g_wf_hi[i * EE + t] = hv;
    g_wf_lo[i * EE + t] = __float2bfloat16(acc - __bfloat162float(hv));

    s_red[t] = s_pw[t] * bout[t];
    __syncthreads();
    for (int off = 128; off > 0; off >>= 1) {
        if (t < off) s_red[t] += s_red[t + off];
        __syncthreads();
    }
    if (t == 0) g_bf[i] = s_red[0];
}

// ---------------------------------------------------------------------------
// HMMA split-bf16 GEMM (unchanged from R9; proven 63us/21us).
// ---------------------------------------------------------------------------
#define STAGE_BYTES 65536
#define GEMM_SMEM_BYTES (2 * STAGE_BYTES)

__device__ __forceinline__ void load_stage(uint32_t sbase, int stage,
                                           const __nv_bfloat16* __restrict__ Ahi,
                                           const __nv_bfloat16* __restrict__ Alo,
                                           const __nv_bfloat16* __restrict__ Bhi,
                                           const __nv_bfloat16* __restrict__ Blo,
                                           int m0, int n0, int kc, int tid) {
    const uint32_t dst = sbase + stage * STAGE_BYTES;
    const __nv_bfloat16* __restrict__ srcs[4] = {
        Ahi + (size_t)m0 * 256, Alo + (size_t)m0 * 256,
        Bhi + (size_t)n0 * 256, Blo + (size_t)n0 * 256 };
#pragma unroll
    for (int arr = 0; arr < 4; arr++) {
        const __nv_bfloat16* __restrict__ s = srcs[arr];
#pragma unroll
        for (int c = 0; c < 4; c++) {             // 1024 16B-chunks / 256 thr
            const int idx = c * 256 + tid;
            const int row = idx >> 3;
            const int k16 = idx & 7;
            const uint32_t soff = (uint32_t)(row << 7) + (uint32_t)((k16 ^ (row & 7)) << 4);
            cp_async16(dst + arr * 16384 + soff,
                       s + (size_t)row * 256 + kc * 64 + k16 * 8);
        }
    }
    CP_COMMIT();
}

__global__ __launch_bounds__(256, 1)
void tc_gemm_kernel(const __nv_bfloat16* __restrict__ Ahi, const __nv_bfloat16* __restrict__ Alo,
                    const __nv_bfloat16* __restrict__ Bhi, const __nv_bfloat16* __restrict__ Blo,
                    const float* __restrict__ bias, float* __restrict__ C, int Ntot) {
    extern __shared__ char dsm[];
    const uint32_t sbase = smem_u32(dsm);

    const int tid = threadIdx.x;
    const int wid = tid >> 5;
    const int lane = tid & 31;
    const int n0 = blockIdx.x * 128;
    const int m0 = blockIdx.y * 128;
    const int wm = wid >> 1;     // 0..3 -> M offset wm*32
    const int wn = wid & 1;      // 0..1 -> N offset wn*64

    float acc[2][8][4];
#pragma unroll
    for (int mt = 0; mt < 2; mt++)
#pragma unroll
        for (int nt = 0; nt < 8; nt++)
#pragma unroll
            for (int e = 0; e < 4; e++) acc[mt][nt][e] = 0.f;

    load_stage(sbase, 0, Ahi, Alo, Bhi, Blo, m0, n0, 0, tid);

    const int q = lane >> 3;     // ldmatrix quad
    const int r = lane & 7;

    for (int kc = 0; kc < 4; kc++) {
        if (kc < 3) {
            load_stage(sbase, (kc + 1) & 1, Ahi, Alo, Bhi, Blo, m0, n0, kc + 1, tid);
            asm volatile("cp.async.wait_group 1;" ::: "memory");
        } else {
            asm volatile("cp.async.wait_group 0;" ::: "memory");
        }
        __syncthreads();

        const uint32_t st = sbase + (kc & 1) * STAGE_BYTES;
#pragma unroll
        for (int s = 0; s < 4; s++) {
            uint32_t aHi[2][4], aLo[2][4];
#pragma unroll
            for (int mt = 0; mt < 2; mt++) {
                const int arow = wm * 32 + mt * 16 + ((q & 1) << 3) + r;
                const int ac = 2 * s + (q >> 1);
                const uint32_t ad = st + (uint32_t)(arow << 7) + (uint32_t)((ac ^ (arow & 7)) << 4);
                LDSM_X4(aHi[mt][0], aHi[mt][1], aHi[mt][2], aHi[mt][3], ad);
                LDSM_X4(aLo[mt][0], aLo[mt][1], aLo[mt][2], aLo[mt][3], ad + 16384);
            }
            uint32_t bHi[8][2], bLo[8][2];
#pragma unroll
            for (int p = 0; p < 4; p++) {
                const int brow = wn * 64 + p * 16 + ((q >> 1) << 3) + r;
                const int bc = 2 * s + (q & 1);
                const uint32_t bd = st + 32768u + (uint32_t)(brow << 7) + (uint32_t)((bc ^ (brow & 7)) << 4);
                uint32_t t0, t1, t2, t3;
                LDSM_X4(t0, t1, t2, t3, bd);
                bHi[2 * p][0] = t0; bHi[2 * p][1] = t1;
                bHi[2 * p + 1][0] = t2; bHi[2 * p + 1][1] = t3;
                LDSM_X4(t0, t1, t2, t3, bd + 16384);
                bLo[2 * p][0] = t0; bLo[2 * p][1] = t1;
                bLo[2 * p + 1][0] = t2; bLo[2 * p + 1][1] = t3;
            }
#pragma unroll
            for (int mt = 0; mt < 2; mt++)
#pragma unroll
                for (int nt = 0; nt < 8; nt++) {
                    mma16816(acc[mt][nt], aHi[mt], bHi[nt]);
                    mma16816(acc[mt][nt], aHi[mt], bLo[nt]);
                    mma16816(acc[mt][nt], aLo[mt], bHi[nt]);
                }
        }
        __syncthreads();
    }

    const int r_base = m0 + wm * 32 + (lane >> 2);
    const int c_base = n0 + wn * 64 + (lane & 3) * 2;
    float2 bv[8];
#pragma unroll
    for (int nt = 0; nt < 8; nt++)
        bv[nt] = *reinterpret_cast<const float2*>(bias + c_base + nt * 8);
#pragma unroll
    for (int mt = 0; mt < 2; mt++) {
        const int rw = r_base + mt * 16;
#pragma unroll
        for (int nt = 0; nt < 8; nt++) {
            float2 v0, v1;
            v0.x = acc[mt][nt][0] + bv[nt].x;
            v0.y = acc[mt][nt][1] + bv[nt].y;
            v1.x = acc[mt][nt][2] + bv[nt].x;
            v1.y = acc[mt][nt][3] + bv[nt].y;
            *reinterpret_cast<float2*>(C + (size_t)rw * Ntot + c_base + nt * 8) = v0;
            *reinterpret_cast<float2*>(C + (size_t)(rw + 8) * Ntot + c_base + nt * 8) = v1;
        }
    }
}

// ---------------------------------------------------------------------------
// Local-window attention, RESTRUCTURED for occupancy:
//  - 512 threads (16 warps), each warp handles 4 queries.
//  - One shared K/V buffer (59KB) time-multiplexed: load K -> scores+softmax
//    into sW -> load V over K -> PV.  Total smem 88KB -> 2 blocks/SM,
//    32 resident warps/SM (was 8).
//  - Q hoisted in two 16-register halves (caps regs for 2-block occupancy).
// ---------------------------------------------------------------------------
#define ATTN_SMEM_FLOATS (448 * 33 + 64 * 32 + 64 * 80)
#define ATTN_SMEM_BYTES (ATTN_SMEM_FLOATS * 4)

__global__ __launch_bounds__(512, 2) void attn_kernel() {
    extern __shared__ float smem[];
    float* sKV = smem;                   // [448][33]  (K, then V)
    float* sQ = sKV + 448 * 33;          // [64][32]
    float* sW = sQ + 64 * 32;            // [64 queries][80]

    const int bid = blockIdx.x;          // b*128 + h*16 + r
    const int rr = bid & 15;
    const int hh = (bid >> 4) & 7;
    const int b = bid >> 7;
    const int tid = threadIdx.x;

    const int rlo = max(0, rr - 3);
    const int rhi = min(IH - 1, rr + 3);
    const int nrows = rhi - rlo + 1;
    const int nkeysKV = nrows * IW;

    const float* __restrict__ qkvb = g_qkv + (size_t)b * LSEQ * (3 * EE);

    // ---- Phase 1: load K halo + Q
    for (int e = tid; e < nkeysKV * 32; e += 512) {
        const int key = e >> 5;
        const int d = e & 31;
        const int l = (rlo + (key >> 6)) * IW + (key & 63);
        sKV[key * 33 + d] = qkvb[(size_t)l * (3 * EE) + EE + hh * DHH + d];
    }
    for (int e = tid; e < 64 * 32; e += 512) {
        sQ[e] = qkvb[(size_t)(rr * IW + (e >> 5)) * (3 * EE) + hh * DHH + (e & 31)];
    }
    __syncthreads();

    const int w = tid >> 5;              // 0..15
    const int lane = tid & 31;
    const float scale = 0.17677669529663687f;  // 1/sqrt(32)
    const size_t ctx_base = ((size_t)b * LSEQ + rr * IW) * EE + hh * DHH + lane;

    // ---- Phase 2: scores + softmax -> sW  (warp w: queries 4w..4w+3)
    for (int qi = 0; qi < 4; qi++) {
        const int c = w * 4 + qi;
        const int clo = max(0, c - 5);
        const int chi = min(IW - 1, c + 5);
        const int nc = chi - clo + 1;
        const int nk = nrows * nc;       // <= 77
        float* myW = sW + c * 80;

        float part[3] = {0.f, 0.f, 0.f};
        const float* qp = sQ + c * 32;
#pragma unroll
        for (int half = 0; half < 2; half++) {
            float qh[16];
#pragma unroll
            for (int d = 0; d < 16; d++) qh[d] = qp[half * 16 + d];
            int cnt = 0;
            for (int i = lane; i < nk; i += 32) {
                const int kr = i / nc;
                const int kcc = clo + (i - kr * nc);
                const float* kp = sKV + (kr * IW + kcc) * 33 + half * 16;
                float dot = 0.f;
#pragma unroll
                for (int d = 0; d < 16; d++) dot += qh[d] * kp[d];
                part[cnt++] += dot;
            }
        }
        float svv[3];
        int cnt = (nk - lane + 31) / 32; if (cnt < 0) cnt = 0;
        for (int j = 0; j < 3; j++) svv[j] = part[j] * scale;

        float m = -1e30f;
        for (int j = 0; j < cnt; j++) m = fmaxf(m, svv[j]);
#pragma unroll
        for (int off = 16; off; off >>= 1) m = fmaxf(m, __shfl_xor_sync(0xffffffffu, m, off));
        float ssum = 0.f;
        for (int j = 0; j < cnt; j++) { svv[j] = __expf(svv[j] - m); ssum += svv[j]; }
#pragma unroll
        for (int off = 16; off; off >>= 1) ssum += __shfl_xor_sync(0xffffffffu, ssum, off);
        const float inv = 1.f / ssum;
        cnt = 0;
        for (int i = lane; i < nk; i += 32) myW[i] = svv[cnt++] * inv;
    }
    __syncthreads();

    // ---- Phase 3: overwrite K with V halo
    for (int e = tid; e < nkeysKV * 32; e += 512) {
        const int key = e >> 5;
        const int d = e & 31;
        const int l = (rlo + (key >> 6)) * IW + (key & 63);
        sKV[key * 33 + d] = qkvb[(size_t)l * (3 * EE) + 2 * EE + hh * DHH + d];
    }
    __syncthreads();

    // ---- Phase 4: PV (lane = dim)
    for (int qi = 0; qi < 4; qi++) {
        const int c = w * 4 + qi;
        const int clo = max(0, c - 5);
        const int chi = min(IW - 1, c + 5);
        const int nc = chi - clo + 1;
        const float* myW = sW + c * 80;

        float acc = 0.f;
        int i = 0;
        for (int kr = 0; kr < nrows; kr++) {
            const float* vp = sKV + (kr * IW + clo) * 33 + lane;
            for (int kcc = 0; kcc < nc; kcc++) { acc += myW[i] * vp[kcc * 33]; i++; }
        }
        const size_t oi = ctx_base + (size_t)c * EE;
        __nv_bfloat16 hv = __float2bfloat16(acc);
        g_ctx_hi[oi] = hv;
        g_ctx_lo[oi] = __float2bfloat16(acc - __bfloat162float(hv));
    }
}

// ---------------------------------------------------------------------------
extern "C" void kernel_launch(void* const* d_in, const int* in_sizes, int n_in,
                              void* d_out, int out_size) {
    const float* patch_embed = (const float*)d_in[0];  // [16,1024,256]
    const float* in_proj_w   = (const float*)d_in[1];  // [768,256]
    const float* in_proj_b   = (const float*)d_in[2];  // [768]
    const float* out_proj_w  = (const float*)d_in[3];  // [256,256]
    const float* out_proj_b  = (const float*)d_in[4];  // [256]
    const float* proj_w      = (const float*)d_in[5];  // [256,256]
    float* out = (float*)d_out;                        // [16,1024,256]

    static bool init_done = false;
    static void *p_xhi, *p_xlo, *p_wqhi, *p_wqlo, *p_wfhi, *p_wflo, *p_bf, *p_chi, *p_clo, *p_qkv;
    if (!init_done) {
        cudaFuncSetAttribute(attn_kernel, cudaFuncAttributeMaxDynamicSharedMemorySize, ATTN_SMEM_BYTES);
        cudaFuncSetAttribute(tc_gemm_kernel, cudaFuncAttributeMaxDynamicSharedMemorySize, GEMM_SMEM_BYTES);
        cudaGetSymbolAddress(&p_xhi,  g_x_hi);
        cudaGetSymbolAddress(&p_xlo,  g_x_lo);
        cudaGetSymbolAddress(&p_wqhi, g_wq_hi);
        cudaGetSymbolAddress(&p_wqlo, g_wq_lo);
        cudaGetSymbolAddress(&p_wfhi, g_wf_hi);
        cudaGetSymbolAddress(&p_wflo, g_wf_lo);
        cudaGetSymbolAddress(&p_bf,   g_bf);
        cudaGetSymbolAddress(&p_chi,  g_ctx_hi);
        cudaGetSymbolAddress(&p_clo,  g_ctx_lo);
        cudaGetSymbolAddress(&p_qkv,  g_qkv);
        init_done = true;
    }

    // bf16 hi/lo splits of activations and qkv weights
    split_kernel<<<(M_ROWS * EE / 4 + 255) / 256, 256>>>(
        patch_embed, (__nv_bfloat16*)p_xhi, (__nv_bfloat16*)p_xlo, M_ROWS * EE / 4);
    split_kernel<<<(3 * EE * EE / 4 + 255) / 256, 256>>>(
        in_proj_w, (__nv_bfloat16*)p_wqhi, (__nv_bfloat16*)p_wqlo, 3 * EE * EE / 4);
    // fused output projection weights (hi/lo) + fused bias
    fuse_kernel<<<EE, 256>>>(proj_w, out_proj_w, out_proj_b);
    // QKV projection on tensor cores (HMMA) -> fp32 g_qkv
    tc_gemm_kernel<<<dim3(6, M_ROWS / 128), 256, GEMM_SMEM_BYTES>>>(
        (const __nv_bfloat16*)p_xhi, (const __nv_bfloat16*)p_xlo,
        (const __nv_bfloat16*)p_wqhi, (const __nv_bfloat16*)p_wqlo,
        in_proj_b, (float*)p_qkv, 3 * EE);
    // local attention -> bf16 hi/lo ctx
    attn_kernel<<<BB * HH * IH, 512, ATTN_SMEM_BYTES>>>();
    // fused output projection on tensor cores straight into d_out
    tc_gemm_kernel<<<dim3(2, M_ROWS / 128), 256, GEMM_SMEM_BYTES>>>(
        (const __nv_bfloat16*)p_chi, (const __nv_bfloat16*)p_clo,
        (const __nv_bfloat16*)p_wfhi, (const __nv_bfloat16*)p_wflo,
        (const float*)p_bf, out, EE);
}

// round 12
// speedup vs baseline: 4.1642x; 1.4488x over previous
#include <cuda_runtime.h>
#include <cuda_bf16.h>
#include <cuda_fp16.h>
#include <cstdint>

// Problem constants
#define IH 16
#define IW 64
#define LSEQ 1024        // IH*IW
#define EE 256
#define BB 16
#define HH 8
#define DHH 32           // EE / HH
#define M_ROWS (BB*LSEQ) // 16384

// ---------------------------------------------------------------------------
// Base-ISA helpers (sm_80-era: work on plain sm_103 target; NO tcgen05)
// ---------------------------------------------------------------------------
__device__ __forceinline__ uint32_t smem_u32(const void* p) {
    uint32_t a;
    asm("{ .reg .u64 t; cvta.to.shared.u64 t, %1; cvt.u32.u64 %0, t; }" : "=r"(a) : "l"(p));
    return a;
}
__device__ __forceinline__ void cp_async16(uint32_t saddr, const void* g) {
    asm volatile("cp.async.cg.shared.global [%0], [%1], 16;" :: "r"(saddr), "l"(g));
}
#define CP_COMMIT() asm volatile("cp.async.commit_group;" ::: "memory")

#define LDSM_X4(r0, r1, r2, r3, addr) \
    asm volatile("ldmatrix.sync.aligned.m8n8.x4.shared.b16 {%0,%1,%2,%3}, [%4];" \
        : "=r"(r0), "=r"(r1), "=r"(r2), "=r"(r3) : "r"(addr))

__device__ __forceinline__ void mma16816(float* d, const uint32_t* a, const uint32_t* b) {
    asm volatile(
        "mma.sync.aligned.m16n8k16.row.col.f32.bf16.bf16.f32 "
        "{%0,%1,%2,%3},{%4,%5,%6,%7},{%8,%9},{%0,%1,%2,%3};"
        : "+f"(d[0]), "+f"(d[1]), "+f"(d[2]), "+f"(d[3])
        : "r"(a[0]), "r"(a[1]), "r"(a[2]), "r"(a[3]), "r"(b[0]), "r"(b[1]));
}
// fp16 variant for attention
__device__ __forceinline__ void mma16816h(float* d, const uint32_t* a, const uint32_t* b) {
    asm volatile(
        "mma.sync.aligned.m16n8k16.row.col.f32.f16.f16.f32 "
        "{%0,%1,%2,%3},{%4,%5,%6,%7},{%8,%9},{%0,%1,%2,%3};"
        : "+f"(d[0]), "+f"(d[1]), "+f"(d[2]), "+f"(d[3])
        : "r"(a[0]), "r"(a[1]), "r"(a[2]), "r"(a[3]), "r"(b[0]), "r"(b[1]));
}

// ---------------------------------------------------------------------------
// Scratch (__device__ globals; no allocation allowed)
// ---------------------------------------------------------------------------
__device__ float          g_qkv[(size_t)M_ROWS * 3 * EE];   // fp32 for attention
__device__ __nv_bfloat16  g_x_hi[(size_t)M_ROWS * EE];
__device__ __nv_bfloat16  g_x_lo[(size_t)M_ROWS * EE];
__device__ __nv_bfloat16  g_wq_hi[3 * EE * EE];
__device__ __nv_bfloat16  g_wq_lo[3 * EE * EE];
__device__ __nv_bfloat16  g_wf_hi[EE * EE];
__device__ __nv_bfloat16  g_wf_lo[EE * EE];
__device__ float          g_bf[EE];
__device__ __nv_bfloat16  g_ctx_hi[(size_t)M_ROWS * EE];
__device__ __nv_bfloat16  g_ctx_lo[(size_t)M_ROWS * EE];

// ---------------------------------------------------------------------------
// fp32 -> bf16 hi/lo split (elementwise, vectorized x4)
// ---------------------------------------------------------------------------
__global__ void split_kernel(const float* __restrict__ src,
                             __nv_bfloat16* __restrict__ hi,
                             __nv_bfloat16* __restrict__ lo, int n4) {
    int i = blockIdx.x * blockDim.x + threadIdx.x;
    if (i >= n4) return;
    float4 x = reinterpret_cast<const float4*>(src)[i];
    __nv_bfloat16 h0 = __float2bfloat16(x.x);
    __nv_bfloat16 h1 = __float2bfloat16(x.y);
    __nv_bfloat16 h2 = __float2bfloat16(x.z);
    __nv_bfloat16 h3 = __float2bfloat16(x.w);
    __nv_bfloat162 ha; ha.x = h0; ha.y = h1;
    __nv_bfloat162 hb; hb.x = h2; hb.y = h3;
    reinterpret_cast<__nv_bfloat162*>(hi)[2 * i]     = ha;
    reinterpret_cast<__nv_bfloat162*>(hi)[2 * i + 1] = hb;
    __nv_bfloat162 la, lb;
    la.x = __float2bfloat16(x.x - __bfloat162float(h0));
    la.y = __float2bfloat16(x.y - __bfloat162float(h1));
    lb.x = __float2bfloat16(x.z - __bfloat162float(h2));
    lb.y = __float2bfloat16(x.w - __bfloat162float(h3));
    reinterpret_cast<__nv_bfloat162*>(lo)[2 * i]     = la;
    reinterpret_cast<__nv_bfloat162*>(lo)[2 * i + 1] = lb;
}

// ---------------------------------------------------------------------------
// Fuse output projections: W_f = proj_w @ out_proj_w (emit bf16 hi/lo),
// b_f = proj_w @ out_proj_b (fp32).
// ---------------------------------------------------------------------------
__global__ void fuse_kernel(const float* __restrict__ wproj,
                            const float* __restrict__ wout,
                            const float* __restrict__ bout) {
    __shared__ float s_pw[EE];
    __shared__ float s_red[256];
    const int i = blockIdx.x;
    const int t = threadIdx.x;
    s_pw[t] = wproj[i * EE + t];
    __syncthreads();
    float acc = 0.f;
#pragma unroll 8
    for (int k = 0; k < EE; k++) acc += s_pw[k] * wout[k * EE + t];
    __nv_bfloat16 hv = __float2bfloat16(acc);
    g_wf_hi[i * EE + t] = hv;
    g_wf_lo[i * EE + t] = __float2bfloat16(acc - __bfloat162float(hv));

    s_red[t] = s_pw[t] * bout[t];
    __syncthreads();
    for (int off = 128; off > 0; off >>= 1) {
        if (t < off) s_red[t] += s_red[t + off];
        __syncthreads();
    }
    if (t == 0) g_bf[i] = s_red[0];
}

// ---------------------------------------------------------------------------
// HMMA split-bf16 GEMM (unchanged; proven 63us/21us).
// ---------------------------------------------------------------------------
#define STAGE_BYTES 65536
#define GEMM_SMEM_BYTES (2 * STAGE_BYTES)

__device__ __forceinline__ void load_stage(uint32_t sbase, int stage,
                                           const __nv_bfloat16* __restrict__ Ahi,
                                           const __nv_bfloat16* __restrict__ Alo,
                                           const __nv_bfloat16* __restrict__ Bhi,
                                           const __nv_bfloat16* __restrict__ Blo,
                                           int m0, int n0, int kc, int tid) {
    const uint32_t dst = sbase + stage * STAGE_BYTES;
    const __nv_bfloat16* __restrict__ srcs[4] = {
        Ahi + (size_t)m0 * 256, Alo + (size_t)m0 * 256,
        Bhi + (size_t)n0 * 256, Blo + (size_t)n0 * 256 };
#pragma unroll
    for (int arr = 0; arr < 4; arr++) {
        const __nv_bfloat16* __restrict__ s = srcs[arr];
#pragma unroll
        for (int c = 0; c < 4; c++) {
            const int idx = c * 256 + tid;
            const int row = idx >> 3;
            const int k16 = idx & 7;
            const uint32_t soff = (uint32_t)(row << 7) + (uint32_t)((k16 ^ (row & 7)) << 4);
            cp_async16(dst + arr * 16384 + soff,
                       s + (size_t)row * 256 + kc * 64 + k16 * 8);
        }
    }
    CP_COMMIT();
}

__global__ __launch_bounds__(256, 1)
void tc_gemm_kernel(const __nv_bfloat16* __restrict__ Ahi, const __nv_bfloat16* __restrict__ Alo,
                    const __nv_bfloat16* __restrict__ Bhi, const __nv_bfloat16* __restrict__ Blo,
                    const float* __restrict__ bias, float* __restrict__ C, int Ntot) {
    extern __shared__ char dsm[];
    const uint32_t sbase = smem_u32(dsm);

    const int tid = threadIdx.x;
    const int wid = tid >> 5;
    const int lane = tid & 31;
    const int n0 = blockIdx.x * 128;
    const int m0 = blockIdx.y * 128;
    const int wm = wid >> 1;
    const int wn = wid & 1;

    float acc[2][8][4];
#pragma unroll
    for (int mt = 0; mt < 2; mt++)
#pragma unroll
        for (int nt = 0; nt < 8; nt++)
#pragma unroll
            for (int e = 0; e < 4; e++) acc[mt][nt][e] = 0.f;

    load_stage(sbase, 0, Ahi, Alo, Bhi, Blo, m0, n0, 0, tid);

    const int q = lane >> 3;
    const int r = lane & 7;

    for (int kc = 0; kc < 4; kc++) {
        if (kc < 3) {
            load_stage(sbase, (kc + 1) & 1, Ahi, Alo, Bhi, Blo, m0, n0, kc + 1, tid);
            asm volatile("cp.async.wait_group 1;" ::: "memory");
        } else {
            asm volatile("cp.async.wait_group 0;" ::: "memory");
        }
        __syncthreads();

        const uint32_t st = sbase + (kc & 1) * STAGE_BYTES;
#pragma unroll
        for (int s = 0; s < 4; s++) {
            uint32_t aHi[2][4], aLo[2][4];
#pragma unroll
            for (int mt = 0; mt < 2; mt++) {
                const int arow = wm * 32 + mt * 16 + ((q & 1) << 3) + r;
                const int ac = 2 * s + (q >> 1);
                const uint32_t ad = st + (uint32_t)(arow << 7) + (uint32_t)((ac ^ (arow & 7)) << 4);
                LDSM_X4(aHi[mt][0], aHi[mt][1], aHi[mt][2], aHi[mt][3], ad);
                LDSM_X4(aLo[mt][0], aLo[mt][1], aLo[mt][2], aLo[mt][3], ad + 16384);
            }
            uint32_t bHi[8][2], bLo[8][2];
#pragma unroll
            for (int p = 0; p < 4; p++) {
                const int brow = wn * 64 + p * 16 + ((q >> 1) << 3) + r;
                const int bc = 2 * s + (q & 1);
                const uint32_t bd = st + 32768u + (uint32_t)(brow << 7) + (uint32_t)((bc ^ (brow & 7)) << 4);
                uint32_t t0, t1, t2, t3;
                LDSM_X4(t0, t1, t2, t3, bd);
                bHi[2 * p][0] = t0; bHi[2 * p][1] = t1;
                bHi[2 * p + 1][0] = t2; bHi[2 * p + 1][1] = t3;
                LDSM_X4(t0, t1, t2, t3, bd + 16384);
                bLo[2 * p][0] = t0; bLo[2 * p][1] = t1;
                bLo[2 * p + 1][0] = t2; bLo[2 * p + 1][1] = t3;
            }
#pragma unroll
            for (int mt = 0; mt < 2; mt++)
#pragma unroll
                for (int nt = 0; nt < 8; nt++) {
                    mma16816(acc[mt][nt], aHi[mt], bHi[nt]);
                    mma16816(acc[mt][nt], aHi[mt], bLo[nt]);
                    mma16816(acc[mt][nt], aLo[mt], bHi[nt]);
                }
        }
        __syncthreads();
    }

    const int r_base = m0 + wm * 32 + (lane >> 2);
    const int c_base = n0 + wn * 64 + (lane & 3) * 2;
    float2 bv[8];
#pragma unroll
    for (int nt = 0; nt < 8; nt++)
        bv[nt] = *reinterpret_cast<const float2*>(bias + c_base + nt * 8);
#pragma unroll
    for (int mt = 0; mt < 2; mt++) {
        const int rw = r_base + mt * 16;
#pragma unroll
        for (int nt = 0; nt < 8; nt++) {
            float2 v0, v1;
            v0.x = acc[mt][nt][0] + bv[nt].x;
            v0.y = acc[mt][nt][1] + bv[nt].y;
            v1.x = acc[mt][nt][2] + bv[nt].x;
            v1.y = acc[mt][nt][3] + bv[nt].y;
            *reinterpret_cast<float2*>(C + (size_t)rw * Ntot + c_base + nt * 8) = v0;
            *reinterpret_cast<float2*>(C + (size_t)(rw + 8) * Ntot + c_base + nt * 8) = v1;
        }
    }
}

// ---------------------------------------------------------------------------
// HMMA attention. One block per (b, h, image_row): dense 64x448 tile.
//   S = Qf16[64,32] @ Kf16[448,32]^T  (fp32 acc, mask in-fragment)
//   softmax in fragments (fp32; cross-warp reductions via smem)
//   P fp16 -> smem (overlays K/Q), ctx = P @ V (V^T fp16 in smem)
// 512 threads / 16 warps, occupancy 1 (register-bound).
// Smem layout (bytes):
//   [0,58368)      union{ Q 64x80 @0 ; K 456x80 @5120 | P 64x912 @0 }
//   [58368,87552)  V^T 32x912
//   [87552,89600)  redM 64x8 f32
//   [89600,91648)  redS 64x8 f32
// ---------------------------------------------------------------------------
#define AT_SQ   0
#define AT_SK   5120
#define AT_SP   0
#define AT_SVT  58368
#define AT_REDM 87552
#define AT_REDS 89600
#define AT_SMEM_BYTES 91648

__global__ __launch_bounds__(512, 1) void attn_kernel() {
    extern __shared__ char sm[];
    const uint32_t sb = smem_u32(sm);
    float* redM = reinterpret_cast<float*>(sm + AT_REDM);
    float* redS = reinterpret_cast<float*>(sm + AT_REDS);

    const int bid = blockIdx.x;          // b*128 + h*16 + rr
    const int rr = bid & 15;
    const int hh = (bid >> 4) & 7;
    const int b = bid >> 7;
    const int tid = threadIdx.x;

    const int rlo = max(0, rr - 3);
    const int rhi = min(IH - 1, rr + 3);
    const int nrows = rhi - rlo + 1;
    const int nk64 = nrows * 64;

    const float* __restrict__ qkvb = g_qkv + (size_t)b * LSEQ * (3 * EE);
    const float scale = 0.17677669529663687f;   // 1/sqrt(32)

    // ---- convert Q (scale folded), K, V^T into fp16 smem
    for (int e = tid; e < 64 * 16; e += 512) {
        const int c = e >> 4, dp = e & 15;
        const float2 v = *reinterpret_cast<const float2*>(
            qkvb + (size_t)(rr * IW + c) * 768 + hh * DHH + dp * 2);
        *reinterpret_cast<__half2*>(sm + AT_SQ + c * 80 + dp * 4) =
            __floats2half2_rn(v.x * scale, v.y * scale);
    }
    for (int e = tid; e < nk64 * 16; e += 512) {
        const int j = e >> 4, dp = e & 15;
        const int l = (rlo + (j >> 6)) * IW + (j & 63);
        const float2 v = *reinterpret_cast<const float2*>(
            qkvb + (size_t)l * 768 + 256 + hh * DHH + dp * 2);
        *reinterpret_cast<__half2*>(sm + AT_SK + j * 80 + dp * 4) =
            __floats2half2_rn(v.x, v.y);
    }
    for (int e = tid; e < nk64 * 32; e += 512) {
        const int j = e >> 5, d = e & 31;
        const int l = (rlo + (j >> 6)) * IW + (j & 63);
        *reinterpret_cast<__half*>(sm + AT_SVT + d * 912 + j * 2) =
            __float2half(qkvb[(size_t)l * 768 + 512 + hh * DHH + d]);
    }
    // zero V^T pad columns (avoid 0*garbage NaN in PV) for border rows
    for (int e = tid + nk64 * 32; e < 448 * 32; e += 512) {
        const int j = e >> 5, d = e & 31;
        *reinterpret_cast<uint16_t*>(sm + AT_SVT + d * 912 + j * 2) = 0;
    }
    __syncthreads();

    const int wid = tid >> 5;
    const int lane = tid & 31;
    const int q = lane >> 3, r = lane & 7;

    // ================= QK^T =================
    // warp = (g: m-half of 32 rows, w8: 56-col slice); acc 2 m16 x 7 n8
    const int g = wid >> 3;
    const int w8 = wid & 7;
    float acc[2][7][4];
#pragma unroll
    for (int m = 0; m < 2; m++)
#pragma unroll
        for (int n = 0; n < 7; n++)
#pragma unroll
            for (int e = 0; e < 4; e++) acc[m][n][e] = 0.f;

#pragma unroll
    for (int s = 0; s < 2; s++) {                 // k16 steps over dh=32
        uint32_t af[2][4];
#pragma unroll
        for (int m = 0; m < 2; m++) {
            const int arow = g * 32 + m * 16 + ((q & 1) << 3) + r;
            const int ac = 2 * s + (q >> 1);
            LDSM_X4(af[m][0], af[m][1], af[m][2], af[m][3],
                    sb + AT_SQ + arow * 80 + ac * 16);
        }
#pragma unroll
        for (int p = 0; p < 4; p++) {
            const int brow = w8 * 56 + p * 16 + ((q >> 1) << 3) + r;   // <= 455
            const int bc = 2 * s + (q & 1);
            uint32_t t0, t1, t2, t3;
            LDSM_X4(t0, t1, t2, t3, sb + AT_SK + brow * 80 + bc * 16);
            uint32_t b0[2] = {t0, t1}, b1[2] = {t2, t3};
#pragma unroll
            for (int m = 0; m < 2; m++) {
                mma16816h(acc[m][2 * p], af[m], b0);
                if (2 * p + 1 < 7) mma16816h(acc[m][2 * p + 1], af[m], b1);
            }
        }
    }

    // ---- mask (window + halo-row validity)
    const int qrow0 = g * 32 + (lane >> 2);       // +m*16 (+8)
#pragma unroll
    for (int m = 0; m < 2; m++)
#pragma unroll
        for (int n = 0; n < 7; n++)
#pragma unroll
            for (int e = 0; e < 4; e++) {
                const int c = qrow0 + m * 16 + ((e >> 1) << 3);
                const int j = w8 * 56 + n * 8 + ((lane & 3) << 1) + (e & 1);
                const int dc = (j & 63) - c;
                const bool valid = ((j >> 6) < nrows) && (dc >= -5) && (dc <= 5);
                if (!valid) acc[m][n][e] = -1e30f;
            }

    // ---- row max (warp slice) -> smem -> global
    float rmax[2][2];
#pragma unroll
    for (int m = 0; m < 2; m++)
#pragma unroll
        for (int h = 0; h < 2; h++) {
            float mv = -1e30f;
#pragma unroll
            for (int n = 0; n < 7; n++) {
                mv = fmaxf(mv, acc[m][n][2 * h]);
                mv = fmaxf(mv, acc[m][n][2 * h + 1]);
            }
            mv = fmaxf(mv, __shfl_xor_sync(0xffffffffu, mv, 1));
            mv = fmaxf(mv, __shfl_xor_sync(0xffffffffu, mv, 2));
            rmax[m][h] = mv;
        }
    if ((lane & 3) == 0) {
#pragma unroll
        for (int m = 0; m < 2; m++)
#pragma unroll
            for (int h = 0; h < 2; h++) {
                const int row = qrow0 + m * 16 + h * 8;
                redM[row * 8 + w8] = rmax[m][h];
            }
    }
    __syncthreads();
    float gmax[2][2];
#pragma unroll
    for (int m = 0; m < 2; m++)
#pragma unroll
        for (int h = 0; h < 2; h++) {
            const int row = qrow0 + m * 16 + h * 8;
            const float4 a4 = reinterpret_cast<const float4*>(redM + row * 8)[0];
            const float4 b4 = reinterpret_cast<const float4*>(redM + row * 8)[1];
            gmax[m][h] = fmaxf(fmaxf(fmaxf(a4.x, a4.y), fmaxf(a4.z, a4.w)),
                               fmaxf(fmaxf(b4.x, b4.y), fmaxf(b4.z, b4.w)));
        }

    // ---- exp + row sum
    float rsum[2][2] = {{0.f, 0.f}, {0.f, 0.f}};
#pragma unroll
    for (int m = 0; m < 2; m++)
#pragma unroll
        for (int n = 0; n < 7; n++)
#pragma unroll
            for (int e = 0; e < 4; e++) {
                const float ev = __expf(acc[m][n][e] - gmax[m][e >> 1]);
                acc[m][n][e] = ev;
                rsum[m][e >> 1] += ev;
            }
#pragma unroll
    for (int m = 0; m < 2; m++)
#pragma unroll
        for (int h = 0; h < 2; h++) {
            float sv = rsum[m][h];
            sv += __shfl_xor_sync(0xffffffffu, sv, 1);
            sv += __shfl_xor_sync(0xffffffffu, sv, 2);
            rsum[m][h] = sv;
        }
    if ((lane & 3) == 0) {
#pragma unroll
        for (int m = 0; m < 2; m++)
#pragma unroll
            for (int h = 0; h < 2; h++) {
                const int row = qrow0 + m * 16 + h * 8;
                redS[row * 8 + w8] = rsum[m][h];
            }
    }
    __syncthreads();
    float ginv[2][2];
#pragma unroll
    for (int m = 0; m < 2; m++)
#pragma unroll
        for (int h = 0; h < 2; h++) {
            const int row = qrow0 + m * 16 + h * 8;
            const float4 a4 = reinterpret_cast<const float4*>(redS + row * 8)[0];
            const float4 b4 = reinterpret_cast<const float4*>(redS + row * 8)[1];
            ginv[m][h] = 1.f / (a4.x + a4.y + a4.z + a4.w + b4.x + b4.y + b4.z + b4.w);
        }

    // ---- store P fp16 (overlays Q/K; safe: all K/Q reads happened pre-sync)
#pragma unroll
    for (int m = 0; m < 2; m++)
#pragma unroll
        for (int n = 0; n < 7; n++) {
            const int row = qrow0 + m * 16;
            const int j0 = w8 * 56 + n * 8 + ((lane & 3) << 1);
            *reinterpret_cast<__half2*>(sm + AT_SP + row * 912 + j0 * 2) =
                __floats2half2_rn(acc[m][n][0] * ginv[m][0], acc[m][n][1] * ginv[m][0]);
            *reinterpret_cast<__half2*>(sm + AT_SP + (row + 8) * 912 + j0 * 2) =
                __floats2half2_rn(acc[m][n][2] * ginv[m][1], acc[m][n][3] * ginv[m][1]);
        }
    __syncthreads();

    // ================= PV =================
    // warp = (mt: m16 tile, nt: n8 dim-tile); 28 k16 steps over 448 keys
    const int mt = wid >> 2;
    const int nt = wid & 3;
    float o[4] = {0.f, 0.f, 0.f, 0.f};
    for (int s = 0; s < 28; s += 2) {
        uint32_t bt[4];
        LDSM_X4(bt[0], bt[1], bt[2], bt[3],
                sb + AT_SVT + (nt * 8 + r) * 912 + (2 * s + q) * 16);
#pragma unroll
        for (int ss = 0; ss < 2; ss++) {
            uint32_t af[4];
            const int arow = mt * 16 + ((q & 1) << 3) + r;
            const int ac = 2 * (s + ss) + (q >> 1);
            LDSM_X4(af[0], af[1], af[2], af[3], sb + AT_SP + arow * 912 + ac * 16);
            mma16816h(o, af, bt + 2 * ss);
        }
    }

    // ---- epilogue: ctx -> bf16 hi/lo
    const int cq = mt * 16 + (lane >> 2);
    const int d = nt * 8 + ((lane & 3) << 1);
    const size_t base = ((size_t)b * LSEQ + rr * IW) * EE + hh * DHH + d;
#pragma unroll
    for (int h = 0; h < 2; h++) {
        const size_t oi = base + (size_t)(cq + h * 8) * EE;
        const float v0 = o[h * 2], v1 = o[h * 2 + 1];
        __nv_bfloat16 h0 = __float2bfloat16(v0);
        __nv_bfloat16 h1 = __float2bfloat16(v1);
        __nv_bfloat162 hp; hp.x = h0; hp.y = h1;
        __nv_bfloat162 lp;
        lp.x = __float2bfloat16(v0 - __bfloat162float(h0));
        lp.y = __float2bfloat16(v1 - __bfloat162float(h1));
        *reinterpret_cast<__nv_bfloat162*>(g_ctx_hi + oi) = hp;
        *reinterpret_cast<__nv_bfloat162*>(g_ctx_lo + oi) = lp;
    }
}

// ---------------------------------------------------------------------------
extern "C" void kernel_launch(void* const* d_in, const int* in_sizes, int n_in,
                              void* d_out, int out_size) {
    const float* patch_embed = (const float*)d_in[0];  // [16,1024,256]
    const float* in_proj_w   = (const float*)d_in[1];  // [768,256]
    const float* in_proj_b   = (const float*)d_in[2];  // [768]
    const float* out_proj_w  = (const float*)d_in[3];  // [256,256]
    const float* out_proj_b  = (const float*)d_in[4];  // [256]
    const float* proj_w      = (const float*)d_in[5];  // [256,256]
    float* out = (float*)d_out;                        // [16,1024,256]

    static bool init_done = false;
    static void *p_xhi, *p_xlo, *p_wqhi, *p_wqlo, *p_wfhi, *p_wflo, *p_bf, *p_chi, *p_clo, *p_qkv;
    if (!init_done) {
        cudaFuncSetAttribute(attn_kernel, cudaFuncAttributeMaxDynamicSharedMemorySize, AT_SMEM_BYTES);
        cudaFuncSetAttribute(tc_gemm_kernel, cudaFuncAttributeMaxDynamicSharedMemorySize, GEMM_SMEM_BYTES);
        cudaGetSymbolAddress(&p_xhi,  g_x_hi);
        cudaGetSymbolAddress(&p_xlo,  g_x_lo);
        cudaGetSymbolAddress(&p_wqhi, g_wq_hi);
        cudaGetSymbolAddress(&p_wqlo, g_wq_lo);
        cudaGetSymbolAddress(&p_wfhi, g_wf_hi);
        cudaGetSymbolAddress(&p_wflo, g_wf_lo);
        cudaGetSymbolAddress(&p_bf,   g_bf);
        cudaGetSymbolAddress(&p_chi,  g_ctx_hi);
        cudaGetSymbolAddress(&p_clo,  g_ctx_lo);
        cudaGetSymbolAddress(&p_qkv,  g_qkv);
        init_done = true;
    }

    // bf16 hi/lo splits of activations and qkv weights
    split_kernel<<<(M_ROWS * EE / 4 + 255) / 256, 256>>>(
        patch_embed, (__nv_bfloat16*)p_xhi, (__nv_bfloat16*)p_xlo, M_ROWS * EE / 4);
    split_kernel<<<(3 * EE * EE / 4 + 255) / 256, 256>>>(
        in_proj_w, (__nv_bfloat16*)p_wqhi, (__nv_bfloat16*)p_wqlo, 3 * EE * EE / 4);
    // fused output projection weights (hi/lo) + fused bias
    fuse_kernel<<<EE, 256>>>(proj_w, out_proj_w, out_proj_b);
    // QKV projection on tensor cores (HMMA) -> fp32 g_qkv
    tc_gemm_kernel<<<dim3(6, M_ROWS / 128), 256, GEMM_SMEM_BYTES>>>(
        (const __nv_bfloat16*)p_xhi, (const __nv_bfloat16*)p_xlo,
        (const __nv_bfloat16*)p_wqhi, (const __nv_bfloat16*)p_wqlo,
        in_proj_b, (float*)p_qkv, 3 * EE);
    // HMMA local attention -> bf16 hi/lo ctx
    attn_kernel<<<BB * HH * IH, 512, AT_SMEM_BYTES>>>();
    // fused output projection on tensor cores straight into d_out
    tc_gemm_kernel<<<dim3(2, M_ROWS / 128), 256, GEMM_SMEM_BYTES>>>(
        (const __nv_bfloat16*)p_chi, (const __nv_bfloat16*)p_clo,
        (const __nv_bfloat16*)p_wfhi, (const __nv_bfloat16*)p_wflo,
        (const float*)p_bf, out, EE);
}

// round 14
// speedup vs baseline: 4.9516x; 1.1891x over previous
#include <cuda_runtime.h>
#include <cuda_bf16.h>
#include <cuda_fp16.h>
#include <cstdint>

// Problem constants
#define IH 16
#define IW 64
#define LSEQ 1024        // IH*IW
#define EE 256
#define BB 16
#define HH 8
#define DHH 32           // EE / HH
#define M_ROWS (BB*LSEQ) // 16384
#define QKV_SEC ((size_t)BB * HH * LSEQ * DHH)   // halves per q/k/v section

// ---------------------------------------------------------------------------
// Base-ISA helpers (sm_80-era: work on plain sm_103 target; NO tcgen05)
// ---------------------------------------------------------------------------
__device__ __forceinline__ uint32_t smem_u32(const void* p) {
    uint32_t a;
    asm("{ .reg .u64 t; cvta.to.shared.u64 t, %1; cvt.u32.u64 %0, t; }" : "=r"(a) : "l"(p));
    return a;
}
__device__ __forceinline__ void cp_async16(uint32_t saddr, const void* g) {
    asm volatile("cp.async.cg.shared.global [%0], [%1], 16;" :: "r"(saddr), "l"(g));
}
#define CP_COMMIT() asm volatile("cp.async.commit_group;" ::: "memory")

#define LDSM_X4(r0, r1, r2, r3, addr) \
    asm volatile("ldmatrix.sync.aligned.m8n8.x4.shared.b16 {%0,%1,%2,%3}, [%4];" \
        : "=r"(r0), "=r"(r1), "=r"(r2), "=r"(r3) : "r"(addr))
#define LDSM_X4_T(r0, r1, r2, r3, addr) \
    asm volatile("ldmatrix.sync.aligned.m8n8.x4.trans.shared.b16 {%0,%1,%2,%3}, [%4];" \
        : "=r"(r0), "=r"(r1), "=r"(r2), "=r"(r3) : "r"(addr))

__device__ __forceinline__ void mma16816(float* d, const uint32_t* a, const uint32_t* b) {
    asm volatile(
        "mma.sync.aligned.m16n8k16.row.col.f32.bf16.bf16.f32 "
        "{%0,%1,%2,%3},{%4,%5,%6,%7},{%8,%9},{%0,%1,%2,%3};"
        : "+f"(d[0]), "+f"(d[1]), "+f"(d[2]), "+f"(d[3])
        : "r"(a[0]), "r"(a[1]), "r"(a[2]), "r"(a[3]), "r"(b[0]), "r"(b[1]));
}
__device__ __forceinline__ void mma16816h(float* d, const uint32_t* a, const uint32_t* b) {
    asm volatile(
        "mma.sync.aligned.m16n8k16.row.col.f32.f16.f16.f32 "
        "{%0,%1,%2,%3},{%4,%5,%6,%7},{%8,%9},{%0,%1,%2,%3};"
        : "+f"(d[0]), "+f"(d[1]), "+f"(d[2]), "+f"(d[3])
        : "r"(a[0]), "r"(a[1]), "r"(a[2]), "r"(a[3]), "r"(b[0]), "r"(b[1]));
}

// ---------------------------------------------------------------------------
// Scratch (__device__ globals; no allocation allowed)
// ---------------------------------------------------------------------------
__device__ __half         g_qkv16[3 * QKV_SEC];             // fp16 qkv, [sec][b][h][l][32]
__device__ __nv_bfloat16  g_x_hi[(size_t)M_ROWS * EE];
__device__ __nv_bfloat16  g_x_lo[(size_t)M_ROWS * EE];
__device__ __nv_bfloat16  g_wq_hi[3 * EE * EE];
__device__ __nv_bfloat16  g_wq_lo[3 * EE * EE];
__device__ __nv_bfloat16  g_wf_hi[EE * EE];
__device__ __nv_bfloat16  g_wf_lo[EE * EE];
__device__ float          g_bf[EE];
__device__ __nv_bfloat16  g_ctx_hi[(size_t)M_ROWS * EE];
__device__ __nv_bfloat16  g_ctx_lo[(size_t)M_ROWS * EE];

// ---------------------------------------------------------------------------
// fp32 -> bf16 hi/lo split (elementwise, vectorized x4)
// ---------------------------------------------------------------------------
__global__ void split_kernel(const float* __restrict__ src,
                             __nv_bfloat16* __restrict__ hi,
                             __nv_bfloat16* __restrict__ lo, int n4) {
    int i = blockIdx.x * blockDim.x + threadIdx.x;
    if (i >= n4) return;
    float4 x = reinterpret_cast<const float4*>(src)[i];
    __nv_bfloat16 h0 = __float2bfloat16(x.x);
    __nv_bfloat16 h1 = __float2bfloat16(x.y);
    __nv_bfloat16 h2 = __float2bfloat16(x.z);
    __nv_bfloat16 h3 = __float2bfloat16(x.w);
    __nv_bfloat162 ha; ha.x = h0; ha.y = h1;
    __nv_bfloat162 hb; hb.x = h2; hb.y = h3;
    reinterpret_cast<__nv_bfloat162*>(hi)[2 * i]     = ha;
    reinterpret_cast<__nv_bfloat162*>(hi)[2 * i + 1] = hb;
    __nv_bfloat162 la, lb;
    la.x = __float2bfloat16(x.x - __bfloat162float(h0));
    la.y = __float2bfloat16(x.y - __bfloat162float(h1));
    lb.x = __float2bfloat16(x.z - __bfloat162float(h2));
    lb.y = __float2bfloat16(x.w - __bfloat162float(h3));
    reinterpret_cast<__nv_bfloat162*>(lo)[2 * i]     = la;
    reinterpret_cast<__nv_bfloat162*>(lo)[2 * i + 1] = lb;
}

// ---------------------------------------------------------------------------
// Fuse output projections: W_f = proj_w @ out_proj_w (emit bf16 hi/lo),
// b_f = proj_w @ out_proj_b (fp32).
// ---------------------------------------------------------------------------
__global__ void fuse_kernel(const float* __restrict__ wproj,
                            const float* __restrict__ wout,
                            const float* __restrict__ bout) {
    __shared__ float s_pw[EE];
    __shared__ float s_red[256];
    const int i = blockIdx.x;
    const int t = threadIdx.x;
    s_pw[t] = wproj[i * EE + t];
    __syncthreads();
    float acc = 0.f;
#pragma unroll 8
    for (int k = 0; k < EE; k++) acc += s_pw[k] * wout[k * EE + t];
    __nv_bfloat16 hv = __float2bfloat16(acc);
    g_wf_hi[i * EE + t] = hv;
    g_wf_lo[i * EE + t] = __float2bfloat16(acc - __bfloat162float(hv));

    s_red[t] = s_pw[t] * bout[t];
    __syncthreads();
    for (int off = 128; off > 0; off >>= 1) {
        if (t < off) s_red[t] += s_red[t + off];
        __syncthreads();
    }
    if (t == 0) g_bf[i] = s_red[0];
}

// ---------------------------------------------------------------------------
// HMMA split-bf16 GEMM: C[M, Ntot] = A[M,256] @ W[Ntot,256]^T + bias.
// MODE 0: fp32 store to C (out projection).
// MODE 1: fp16 scatter to g_qkv16[sec][b][h][l][d], q section scaled 1/sqrt(dh).
// ---------------------------------------------------------------------------
#define STAGE_BYTES 65536
#define GEMM_SMEM_BYTES (2 * STAGE_BYTES)

__device__ __forceinline__ void load_stage(uint32_t sbase, int stage,
                                           const __nv_bfloat16* __restrict__ Ahi,
                                           const __nv_bfloat16* __restrict__ Alo,
                                           const __nv_bfloat16* __restrict__ Bhi,
                                           const __nv_bfloat16* __restrict__ Blo,
                                           int m0, int n0, int kc, int tid) {
    const uint32_t dst = sbase + stage * STAGE_BYTES;
    const __nv_bfloat16* __restrict__ srcs[4] = {
        Ahi + (size_t)m0 * 256, Alo + (size_t)m0 * 256,
        Bhi + (size_t)n0 * 256, Blo + (size_t)n0 * 256 };
#pragma unroll
    for (int arr = 0; arr < 4; arr++) {
        const __nv_bfloat16* __restrict__ s = srcs[arr];
#pragma unroll
        for (int c = 0; c < 4; c++) {
            const int idx = c * 256 + tid;
            const int row = idx >> 3;
            const int k16 = idx & 7;
            const uint32_t soff = (uint32_t)(row << 7) + (uint32_t)((k16 ^ (row & 7)) << 4);
            cp_async16(dst + arr * 16384 + soff,
                       s + (size_t)row * 256 + kc * 64 + k16 * 8);
        }
    }
    CP_COMMIT();
}

template<int MODE>
__global__ __launch_bounds__(256, 1)
void tc_gemm_kernel(const __nv_bfloat16* __restrict__ Ahi, const __nv_bfloat16* __restrict__ Alo,
                    const __nv_bfloat16* __restrict__ Bhi, const __nv_bfloat16* __restrict__ Blo,
                    const float* __restrict__ bias, float* __restrict__ C, int Ntot) {
    extern __shared__ char dsm[];
    const uint32_t sbase = smem_u32(dsm);

    const int tid = threadIdx.x;
    const int wid = tid >> 5;
    const int lane = tid & 31;
    const int n0 = blockIdx.x * 128;
    const int m0 = blockIdx.y * 128;
    const int wm = wid >> 1;
    const int wn = wid & 1;

    float acc[2][8][4];
#pragma unroll
    for (int mt = 0; mt < 2; mt++)
#pragma unroll
        for (int nt = 0; nt < 8; nt++)
#pragma unroll
            for (int e = 0; e < 4; e++) acc[mt][nt][e] = 0.f;

    load_stage(sbase, 0, Ahi, Alo, Bhi, Blo, m0, n0, 0, tid);

    const int q = lane >> 3;
    const int r = lane & 7;

    for (int kc = 0; kc < 4; kc++) {
        if (kc < 3) {
            load_stage(sbase, (kc + 1) & 1, Ahi, Alo, Bhi, Blo, m0, n0, kc + 1, tid);
            asm volatile("cp.async.wait_group 1;" ::: "memory");
        } else {
            asm volatile("cp.async.wait_group 0;" ::: "memory");
        }
        __syncthreads();

        const uint32_t st = sbase + (kc & 1) * STAGE_BYTES;
#pragma unroll
        for (int s = 0; s < 4; s++) {
            uint32_t aHi[2][4], aLo[2][4];
#pragma unroll
            for (int mt = 0; mt < 2; mt++) {
                const int arow = wm * 32 + mt * 16 + ((q & 1) << 3) + r;
                const int ac = 2 * s + (q >> 1);
                const uint32_t ad = st + (uint32_t)(arow << 7) + (uint32_t)((ac ^ (arow & 7)) << 4);
                LDSM_X4(aHi[mt][0], aHi[mt][1], aHi[mt][2], aHi[mt][3], ad);
                LDSM_X4(aLo[mt][0], aLo[mt][1], aLo[mt][2], aLo[mt][3], ad + 16384);
            }
            uint32_t bHi[8][2], bLo[8][2];
#pragma unroll
            for (int p = 0; p < 4; p++) {
                const int brow = wn * 64 + p * 16 + ((q >> 1) << 3) + r;
                const int bc = 2 * s + (q & 1);
                const uint32_t bd = st + 32768u + (uint32_t)(brow << 7) + (uint32_t)((bc ^ (brow & 7)) << 4);
                uint32_t t0, t1, t2, t3;
                LDSM_X4(t0, t1, t2, t3, bd);
                bHi[2 * p][0] = t0; bHi[2 * p][1] = t1;
                bHi[2 * p + 1][0] = t2; bHi[2 * p + 1][1] = t3;
                LDSM_X4(t0, t1, t2, t3, bd + 16384);
                bLo[2 * p][0] = t0; bLo[2 * p][1] = t1;
                bLo[2 * p + 1][0] = t2; bLo[2 * p + 1][1] = t3;
            }
#pragma unroll
            for (int mt = 0; mt < 2; mt++)
#pragma unroll
                for (int nt = 0; nt < 8; nt++) {
                    mma16816(acc[mt][nt], aHi[mt], bHi[nt]);
                    mma16816(acc[mt][nt], aHi[mt], bLo[nt]);
                    mma16816(acc[mt][nt], aLo[mt], bHi[nt]);
                }
        }
        __syncthreads();
    }

    const int r_base = m0 + wm * 32 + (lane >> 2);
    const int c_base = n0 + wn * 64 + (lane & 3) * 2;
    float2 bv[8];
#pragma unroll
    for (int nt = 0; nt < 8; nt++)
        bv[nt] = *reinterpret_cast<const float2*>(bias + c_base + nt * 8);

    if (MODE == 0) {
#pragma unroll
        for (int mt = 0; mt < 2; mt++) {
            const int rw = r_base + mt * 16;
#pragma unroll
            for (int nt = 0; nt < 8; nt++) {
                float2 v0, v1;
                v0.x = acc[mt][nt][0] + bv[nt].x;
                v0.y = acc[mt][nt][1] + bv[nt].y;
                v1.x = acc[mt][nt][2] + bv[nt].x;
                v1.y = acc[mt][nt][3] + bv[nt].y;
                *reinterpret_cast<float2*>(C + (size_t)rw * Ntot + c_base + nt * 8) = v0;
                *reinterpret_cast<float2*>(C + (size_t)(rw + 8) * Ntot + c_base + nt * 8) = v1;
            }
        }
    } else {
        // fp16 scatter into g_qkv16[sec][b][h][l][32]; q section (blocks 0,1) scaled
        const float bscale = (blockIdx.x < 2) ? 0.17677669529663687f : 1.0f;
#pragma unroll
        for (int mt = 0; mt < 2; mt++) {
            const int rw = r_base + mt * 16;
            const int b_ = rw >> 10;
            const int l0 = rw & 1023;
#pragma unroll
            for (int nt = 0; nt < 8; nt++) {
                const int gc = c_base + nt * 8;
                const int sec = gc >> 8;
                const int h_ = (gc >> 5) & 7;
                const int d_ = gc & 31;
                __half* dst = g_qkv16 + (size_t)((sec * BB + b_) * HH + h_) * (LSEQ * DHH) + d_;
                const float v0x = (acc[mt][nt][0] + bv[nt].x) * bscale;
                const float v0y = (acc[mt][nt][1] + bv[nt].y) * bscale;
                const float v1x = (acc[mt][nt][2] + bv[nt].x) * bscale;
                const float v1y = (acc[mt][nt][3] + bv[nt].y) * bscale;
                *reinterpret_cast<__half2*>(dst + (size_t)l0 * 32) = __floats2half2_rn(v0x, v0y);
                *reinterpret_cast<__half2*>(dst + (size_t)(l0 + 8) * 32) = __floats2half2_rn(v1x, v1y);
            }
        }
    }
}

// ---------------------------------------------------------------------------
// HMMA attention. One block per (b, h, image_row): dense 64x448 tile.
// qkv already fp16 in attention-native layout: phase 1 is pure cp.async,
// with V in a second commit group overlapped with QK^T + softmax.
// Smem (bytes):
//   [0,40960)      Q 64x80 @0 ; K 448x80 @5120   (overlaid by P 64x912 @0)
//   [58368,94208)  V 448x80 (row-natural; PV uses ldmatrix.trans)
//   [94208,96256)  redM 64x8 f32
//   [96256,98304)  redS 64x8 f32
// ---------------------------------------------------------------------------
#define AT_SQ   0
#define AT_SK   5120
#define AT_SP   0
#define AT_SV   58368
#define AT_REDM 94208
#define AT_REDS 96256
#define AT_SMEM_BYTES 98304

__global__ __launch_bounds__(512, 1) void attn_kernel() {
    extern __shared__ char sm[];
    const uint32_t sb = smem_u32(sm);
    float* redM = reinterpret_cast<float*>(sm + AT_REDM);
    float* redS = reinterpret_cast<float*>(sm + AT_REDS);

    const int bid = blockIdx.x;          // b*128 + h*16 + rr
    const int rr = bid & 15;
    const int hh = (bid >> 4) & 7;
    const int b = bid >> 7;
    const int tid = threadIdx.x;

    const int rlo = max(0, rr - 3);
    const int rhi = min(IH - 1, rr + 3);
    const int nrows = rhi - rlo + 1;
    const int nk64 = nrows * 64;

    const __half* __restrict__ gq = g_qkv16 + (size_t)(b * HH + hh) * (LSEQ * DHH);
    const __half* __restrict__ gk = gq + QKV_SEC;
    const __half* __restrict__ gv = gk + QKV_SEC;

    // ---- Phase 1: pure cp.async. Group A: Q+K. Group B: V (overlaps QK^T).
    for (int e = tid; e < 64 * 4; e += 512) {
        const int row = e >> 2, ch = e & 3;
        cp_async16(sb + AT_SQ + row * 80 + ch * 16,
                   gq + (size_t)(rr * IW + row) * 32 + ch * 8);
    }
    for (int e = tid; e < nk64 * 4; e += 512) {
        const int row = e >> 2, ch = e & 3;
        cp_async16(sb + AT_SK + row * 80 + ch * 16,
                   gk + (size_t)(rlo * IW + row) * 32 + ch * 8);
    }
    CP_COMMIT();
    for (int e = tid; e < nk64 * 4; e += 512) {
        const int row = e >> 2, ch = e & 3;
        cp_async16(sb + AT_SV + row * 80 + ch * 16,
                   gv + (size_t)(rlo * IW + row) * 32 + ch * 8);
    }
    CP_COMMIT();
    // zero V pad rows (border blocks): P is 0 there; avoid 0*garbage NaN
    for (int e = tid + nk64 * 4; e < 448 * 4; e += 512) {
        const int row = e >> 2, ch = e & 3;
        *reinterpret_cast<float4*>(sm + AT_SV + row * 80 + ch * 16) =
            make_float4(0.f, 0.f, 0.f, 0.f);
    }
    asm volatile("cp.async.wait_group 1;" ::: "memory");   // Q+K ready
    __syncthreads();

    const int wid = tid >> 5;
    const int lane = tid & 31;
    const int q = lane >> 3, r = lane & 7;

    // ================= QK^T =================
    const int g = wid >> 3;
    const int w8 = wid & 7;
    float acc[2][7][4];
#pragma unroll
    for (int m = 0; m < 2; m++)
#pragma unroll
        for (int n = 0; n < 7; n++)
#pragma unroll
            for (int e = 0; e < 4; e++) acc[m][n][e] = 0.f;

#pragma unroll
    for (int s = 0; s < 2; s++) {
        uint32_t af[2][4];
#pragma unroll
        for (int m = 0; m < 2; m++) {
            const int arow = g * 32 + m * 16 + ((q & 1) << 3) + r;
            const int ac = 2 * s + (q >> 1);
            LDSM_X4(af[m][0], af[m][1], af[m][2], af[m][3],
                    sb + AT_SQ + arow * 80 + ac * 16);
        }
#pragma unroll
        for (int p = 0; p < 4; p++) {
            const int brow = w8 * 56 + p * 16 + ((q >> 1) << 3) + r;
            const int bc = 2 * s + (q & 1);
            uint32_t t0, t1, t2, t3;
            LDSM_X4(t0, t1, t2, t3, sb + AT_SK + brow * 80 + bc * 16);
            uint32_t b0[2] = {t0, t1}, b1[2] = {t2, t3};
#pragma unroll
            for (int m = 0; m < 2; m++) {
                mma16816h(acc[m][2 * p], af[m], b0);
                if (2 * p + 1 < 7) mma16816h(acc[m][2 * p + 1], af[m], b1);
            }
        }
    }

    // ---- mask (window + halo-row validity)
    const int qrow0 = g * 32 + (lane >> 2);
#pragma unroll
    for (int m = 0; m < 2; m++)
#pragma unroll
        for (int n = 0; n < 7; n++)
#pragma unroll
            for (int e = 0; e < 4; e++) {
                const int c = qrow0 + m * 16 + ((e >> 1) << 3);
                const int j = w8 * 56 + n * 8 + ((lane & 3) << 1) + (e & 1);
                const int dc = (j & 63) - c;
                const bool valid = ((j >> 6) < nrows) && (dc >= -5) && (dc <= 5);
                if (!valid) acc[m][n][e] = -1e30f;
            }

    // ---- row max
    float rmax[2][2];
#pragma unroll
    for (int m = 0; m < 2; m++)
#pragma unroll
        for (int h = 0; h < 2; h++) {
            float mv = -1e30f;
#pragma unroll
            for (int n = 0; n < 7; n++) {
                mv = fmaxf(mv, acc[m][n][2 * h]);
                mv = fmaxf(mv, acc[m][n][2 * h + 1]);
            }
            mv = fmaxf(mv, __shfl_xor_sync(0xffffffffu, mv, 1));
            mv = fmaxf(mv, __shfl_xor_sync(0xffffffffu, mv, 2));
            rmax[m][h] = mv;
        }
    if ((lane & 3) == 0) {
#pragma unroll
        for (int m = 0; m < 2; m++)
#pragma unroll
            for (int h = 0; h < 2; h++) {
                const int row = qrow0 + m * 16 + h * 8;
                redM[row * 8 + w8] = rmax[m][h];
            }
    }
    __syncthreads();
    float gmax[2][2];
#pragma unroll
    for (int m = 0; m < 2; m++)
#pragma unroll
        for (int h = 0; h < 2; h++) {
            const int row = qrow0 + m * 16 + h * 8;
            const float4 a4 = reinterpret_cast<const float4*>(redM + row * 8)[0];
            const float4 b4 = reinterpret_cast<const float4*>(redM + row * 8)[1];
            gmax[m][h] = fmaxf(fmaxf(fmaxf(a4.x, a4.y), fmaxf(a4.z, a4.w)),
                               fmaxf(fmaxf(b4.x, b4.y), fmaxf(b4.z, b4.w)));
        }

    // ---- exp + row sum
    float rsum[2][2] = {{0.f, 0.f}, {0.f, 0.f}};
#pragma unroll
    for (int m = 0; m < 2; m++)
#pragma unroll
        for (int n = 0; n < 7; n++)
#pragma unroll
            for (int e = 0; e < 4; e++) {
                const float ev = __expf(acc[m][n][e] - gmax[m][e >> 1]);
                acc[m][n][e] = ev;
                rsum[m][e >> 1] += ev;
            }
#pragma unroll
    for (int m = 0; m < 2; m++)
#pragma unroll
        for (int h = 0; h < 2; h++) {
            float sv = rsum[m][h];
            sv += __shfl_xor_sync(0xffffffffu, sv, 1);
            sv += __shfl_xor_sync(0xffffffffu, sv, 2);
            rsum[m][h] = sv;
        }
    if ((lane & 3) == 0) {
#pragma unroll
        for (int m = 0; m < 2; m++)
#pragma unroll
            for (int h = 0; h < 2; h++) {
                const int row = qrow0 + m * 16 + h * 8;
                redS[row * 8 + w8] = rsum[m][h];
            }
    }
    __syncthreads();
    float ginv[2][2];
#pragma unroll
    for (int m = 0; m < 2; m++)
#pragma unroll
        for (int h = 0; h < 2; h++) {
            const int row = qrow0 + m * 16 + h * 8;
            const float4 a4 = reinterpret_cast<const float4*>(redS + row * 8)[0];
            const float4 b4 = reinterpret_cast<const float4*>(redS + row * 8)[1];
            ginv[m][h] = 1.f / (a4.x + a4.y + a4.z + a4.w + b4.x + b4.y + b4.z + b4.w);
        }

    // ---- store P fp16 (overlays Q/K; all K/Q reads happened pre-sync)
#pragma unroll
    for (int m = 0; m < 2; m++)
#pragma unroll
        for (int n = 0; n < 7; n++) {
            const int row = qrow0 + m * 16;
            const int j0 = w8 * 56 + n * 8 + ((lane & 3) << 1);
            *reinterpret_cast<__half2*>(sm + AT_SP + row * 912 + j0 * 2) =
                __floats2half2_rn(acc[m][n][0] * ginv[m][0], acc[m][n][1] * ginv[m][0]);
            *reinterpret_cast<__half2*>(sm + AT_SP + (row + 8) * 912 + j0 * 2) =
                __floats2half2_rn(acc[m][n][2] * ginv[m][1], acc[m][n][3] * ginv[m][1]);
        }
    asm volatile("cp.async.wait_group 0;" ::: "memory");   // V ready
    __syncthreads();

    // ================= PV =================
    // warp = (mt: m16 tile, nt: n8 dim-tile); 28 k16 steps over 448 keys.
    // B fragments from row-natural V via ldmatrix.trans.
    const int mt = wid >> 2;
    const int nt = wid & 3;
    float o[4] = {0.f, 0.f, 0.f, 0.f};
    for (int s = 0; s < 28; s += 2) {
        uint32_t bt[4];
        LDSM_X4_T(bt[0], bt[1], bt[2], bt[3],
                  sb + AT_SV + (s * 16 + lane) * 80 + nt * 16);
#pragma unroll
        for (int ss = 0; ss < 2; ss++) {
            uint32_t af[4];
            const int arow = mt * 16 + ((q & 1) << 3) + r;
            const int ac = 2 * (s + ss) + (q >> 1);
            LDSM_X4(af[0], af[1], af[2], af[3], sb + AT_SP + arow * 912 + ac * 16);
            mma16816h(o, af, bt + 2 * ss);
        }
    }

    // ---- epilogue: ctx -> bf16 hi/lo
    const int cq = mt * 16 + (lane >> 2);
    const int d = nt * 8 + ((lane & 3) << 1);
    const size_t base = ((size_t)b * LSEQ + rr * IW) * EE + hh * DHH + d;
#pragma unroll
    for (int h = 0; h < 2; h++) {
        const size_t oi = base + (size_t)(cq + h * 8) * EE;
        const float v0 = o[h * 2], v1 = o[h * 2 + 1];
        __nv_bfloat16 h0 = __float2bfloat16(v0);
        __nv_bfloat16 h1 = __float2bfloat16(v1);
        __nv_bfloat162 hp; hp.x = h0; hp.y = h1;
        __nv_bfloat162 lp;
        lp.x = __float2bfloat16(v0 - __bfloat162float(h0));
        lp.y = __float2bfloat16(v1 - __bfloat162float(h1));
        *reinterpret_cast<__nv_bfloat162*>(g_ctx_hi + oi) = hp;
        *reinterpret_cast<__nv_bfloat162*>(g_ctx_lo + oi) = lp;
    }
}

// ---------------------------------------------------------------------------
extern "C" void kernel_launch(void* const* d_in, const int* in_sizes, int n_in,
                              void* d_out, int out_size) {
    const float* patch_embed = (const float*)d_in[0];  // [16,1024,256]
    const float* in_proj_w   = (const float*)d_in[1];  // [768,256]
    const float* in_proj_b   = (const float*)d_in[2];  // [768]
    const float* out_proj_w  = (const float*)d_in[3];  // [256,256]
    const float* out_proj_b  = (const float*)d_in[4];  // [256]
    const float* proj_w      = (const float*)d_in[5];  // [256,256]
    float* out = (float*)d_out;                        // [16,1024,256]

    static bool init_done = false;
    static void *p_xhi, *p_xlo, *p_wqhi, *p_wqlo, *p_wfhi, *p_wflo, *p_bf, *p_chi, *p_clo;
    if (!init_done) {
        cudaFuncSetAttribute(attn_kernel, cudaFuncAttributeMaxDynamicSharedMemorySize, AT_SMEM_BYTES);
        cudaFuncSetAttribute(tc_gemm_kernel<0>, cudaFuncAttributeMaxDynamicSharedMemorySize, GEMM_SMEM_BYTES);
        cudaFuncSetAttribute(tc_gemm_kernel<1>, cudaFuncAttributeMaxDynamicSharedMemorySize, GEMM_SMEM_BYTES);
        cudaGetSymbolAddress(&p_xhi,  g_x_hi);
        cudaGetSymbolAddress(&p_xlo,  g_x_lo);
        cudaGetSymbolAddress(&p_wqhi, g_wq_hi);
        cudaGetSymbolAddress(&p_wqlo, g_wq_lo);
        cudaGetSymbolAddress(&p_wfhi, g_wf_hi);
        cudaGetSymbolAddress(&p_wflo, g_wf_lo);
        cudaGetSymbolAddress(&p_bf,   g_bf);
        cudaGetSymbolAddress(&p_chi,  g_ctx_hi);
        cudaGetSymbolAddress(&p_clo,  g_ctx_lo);
        init_done = true;
    }

    // bf16 hi/lo splits of activations and qkv weights
    split_kernel<<<(M_ROWS * EE / 4 + 255) / 256, 256>>>(
        patch_embed, (__nv_bfloat16*)p_xhi, (__nv_bfloat16*)p_xlo, M_ROWS * EE / 4);
    split_kernel<<<(3 * EE * EE / 4 + 255) / 256, 256>>>(
        in_proj_w, (__nv_bfloat16*)p_wqhi, (__nv_bfloat16*)p_wqlo, 3 * EE * EE / 4);
    // fused output projection weights (hi/lo) + fused bias
    fuse_kernel<<<EE, 256>>>(proj_w, out_proj_w, out_proj_b);
    // QKV projection -> fp16 qkv in attention layout (q pre-scaled)
    tc_gemm_kernel<1><<<dim3(6, M_ROWS / 128), 256, GEMM_SMEM_BYTES>>>(
        (const __nv_bfloat16*)p_xhi, (const __nv_bfloat16*)p_xlo,
        (const __nv_bfloat16*)p_wqhi, (const __nv_bfloat16*)p_wqlo,
        in_proj_b, nullptr, 3 * EE);
    // HMMA local attention -> bf16 hi/lo ctx
    attn_kernel<<<BB * HH * IH, 512, AT_SMEM_BYTES>>>();
    // fused output projection straight into d_out
    tc_gemm_kernel<0><<<dim3(2, M_ROWS / 128), 256, GEMM_SMEM_BYTES>>>(
        (const __nv_bfloat16*)p_chi, (const __nv_bfloat16*)p_clo,
        (const __nv_bfloat16*)p_wfhi, (const __nv_bfloat16*)p_wflo,
        (const float*)p_bf, out, EE);
}

// round 16
// speedup vs baseline: 5.4633x; 1.1033x over previous
#include <cuda_runtime.h>
#include <cuda_bf16.h>
#include <cuda_fp16.h>
#include <cstdint>

// Problem constants
#define IH 16
#define IW 64
#define LSEQ 1024        // IH*IW
#define EE 256
#define BB 16
#define HH 8
#define DHH 32           // EE / HH
#define M_ROWS (BB*LSEQ) // 16384
#define QKV_SEC ((size_t)BB * HH * LSEQ * DHH)   // halves per q/k/v section

// ---------------------------------------------------------------------------
// Base-ISA helpers (sm_80-era: work on plain sm_103 target; NO tcgen05)
// ---------------------------------------------------------------------------
__device__ __forceinline__ uint32_t smem_u32(const void* p) {
    uint32_t a;
    asm("{ .reg .u64 t; cvta.to.shared.u64 t, %1; cvt.u32.u64 %0, t; }" : "=r"(a) : "l"(p));
    return a;
}
__device__ __forceinline__ void cp_async16(uint32_t saddr, const void* g) {
    asm volatile("cp.async.cg.shared.global [%0], [%1], 16;" :: "r"(saddr), "l"(g));
}
#define CP_COMMIT() asm volatile("cp.async.commit_group;" ::: "memory")

#define LDSM_X4(r0, r1, r2, r3, addr) \
    asm volatile("ldmatrix.sync.aligned.m8n8.x4.shared.b16 {%0,%1,%2,%3}, [%4];" \
        : "=r"(r0), "=r"(r1), "=r"(r2), "=r"(r3) : "r"(addr))
#define LDSM_X2(r0, r1, addr) \
    asm volatile("ldmatrix.sync.aligned.m8n8.x2.shared.b16 {%0,%1}, [%2];" \
        : "=r"(r0), "=r"(r1) : "r"(addr))
#define LDSM_X4_T(r0, r1, r2, r3, addr) \
    asm volatile("ldmatrix.sync.aligned.m8n8.x4.trans.shared.b16 {%0,%1,%2,%3}, [%4];" \
        : "=r"(r0), "=r"(r1), "=r"(r2), "=r"(r3) : "r"(addr))

__device__ __forceinline__ void mma16816(float* d, const uint32_t* a, const uint32_t* b) {
    asm volatile(
        "mma.sync.aligned.m16n8k16.row.col.f32.bf16.bf16.f32 "
        "{%0,%1,%2,%3},{%4,%5,%6,%7},{%8,%9},{%0,%1,%2,%3};"
        : "+f"(d[0]), "+f"(d[1]), "+f"(d[2]), "+f"(d[3])
        : "r"(a[0]), "r"(a[1]), "r"(a[2]), "r"(a[3]), "r"(b[0]), "r"(b[1]));
}
__device__ __forceinline__ void mma16816h(float* d, const uint32_t* a, const uint32_t* b) {
    asm volatile(
        "mma.sync.aligned.m16n8k16.row.col.f32.f16.f16.f32 "
        "{%0,%1,%2,%3},{%4,%5,%6,%7},{%8,%9},{%0,%1,%2,%3};"
        : "+f"(d[0]), "+f"(d[1]), "+f"(d[2]), "+f"(d[3])
        : "r"(a[0]), "r"(a[1]), "r"(a[2]), "r"(a[3]), "r"(b[0]), "r"(b[1]));
}

// ---------------------------------------------------------------------------
// Scratch (__device__ globals; no allocation allowed)
// ---------------------------------------------------------------------------
__device__ __half         g_qkv16[3 * QKV_SEC];             // fp16 qkv, [sec][b][h][l][32]
__device__ __nv_bfloat16  g_x_hi[(size_t)M_ROWS * EE];
__device__ __nv_bfloat16  g_x_lo[(size_t)M_ROWS * EE];
__device__ __nv_bfloat16  g_wq_hi[3 * EE * EE];
__device__ __nv_bfloat16  g_wq_lo[3 * EE * EE];
__device__ __nv_bfloat16  g_wf_hi[EE * EE];
__device__ __nv_bfloat16  g_wf_lo[EE * EE];
__device__ float          g_bf[EE];
__device__ __nv_bfloat16  g_ctx_hi[(size_t)M_ROWS * EE];
__device__ __nv_bfloat16  g_ctx_lo[(size_t)M_ROWS * EE];

// ---------------------------------------------------------------------------
// fp32 -> bf16 hi/lo split (elementwise, vectorized x4)
// ---------------------------------------------------------------------------
__global__ void split_kernel(const float* __restrict__ src,
                             __nv_bfloat16* __restrict__ hi,
                             __nv_bfloat16* __restrict__ lo, int n4) {
    int i = blockIdx.x * blockDim.x + threadIdx.x;
    if (i >= n4) return;
    float4 x = reinterpret_cast<const float4*>(src)[i];
    __nv_bfloat16 h0 = __float2bfloat16(x.x);
    __nv_bfloat16 h1 = __float2bfloat16(x.y);
    __nv_bfloat16 h2 = __float2bfloat16(x.z);
    __nv_bfloat16 h3 = __float2bfloat16(x.w);
    __nv_bfloat162 ha; ha.x = h0; ha.y = h1;
    __nv_bfloat162 hb; hb.x = h2; hb.y = h3;
    reinterpret_cast<__nv_bfloat162*>(hi)[2 * i]     = ha;
    reinterpret_cast<__nv_bfloat162*>(hi)[2 * i + 1] = hb;
    __nv_bfloat162 la, lb;
    la.x = __float2bfloat16(x.x - __bfloat162float(h0));
    la.y = __float2bfloat16(x.y - __bfloat162float(h1));
    lb.x = __float2bfloat16(x.z - __bfloat162float(h2));
    lb.y = __float2bfloat16(x.w - __bfloat162float(h3));
    reinterpret_cast<__nv_bfloat162*>(lo)[2 * i]     = la;
    reinterpret_cast<__nv_bfloat162*>(lo)[2 * i + 1] = lb;
}

// ---------------------------------------------------------------------------
// Fuse output projections: W_f = proj_w @ out_proj_w (emit bf16 hi/lo),
// b_f = proj_w @ out_proj_b (fp32).
// ---------------------------------------------------------------------------
__global__ void fuse_kernel(const float* __restrict__ wproj,
                            const float* __restrict__ wout,
                            const float* __restrict__ bout) {
    __shared__ float s_pw[EE];
    __shared__ float s_red[256];
    const int i = blockIdx.x;
    const int t = threadIdx.x;
    s_pw[t] = wproj[i * EE + t];
    __syncthreads();
    float acc = 0.f;
#pragma unroll 8
    for (int k = 0; k < EE; k++) acc += s_pw[k] * wout[k * EE + t];
    __nv_bfloat16 hv = __float2bfloat16(acc);
    g_wf_hi[i * EE + t] = hv;
    g_wf_lo[i * EE + t] = __float2bfloat16(acc - __bfloat162float(hv));

    s_red[t] = s_pw[t] * bout[t];
    __syncthreads();
    for (int off = 128; off > 0; off >>= 1) {
        if (t < off) s_red[t] += s_red[t + off];
        __syncthreads();
    }
    if (t == 0) g_bf[i] = s_red[0];
}

// ---------------------------------------------------------------------------
// HMMA split-bf16 GEMM: C[M, Ntot] = A[M,256] @ W[Ntot,256]^T + bias.
// MODE 0: fp32 store to C (out projection).
// MODE 1: fp16 scatter to g_qkv16[sec][b][h][l][d], q section scaled 1/sqrt(dh).
// ---------------------------------------------------------------------------
#define STAGE_BYTES 65536
#define GEMM_SMEM_BYTES (2 * STAGE_BYTES)

__device__ __forceinline__ void load_stage(uint32_t sbase, int stage,
                                           const __nv_bfloat16* __restrict__ Ahi,
                                           const __nv_bfloat16* __restrict__ Alo,
                                           const __nv_bfloat16* __restrict__ Bhi,
                                           const __nv_bfloat16* __restrict__ Blo,
                                           int m0, int n0, int kc, int tid) {
    const uint32_t dst = sbase + stage * STAGE_BYTES;
    const __nv_bfloat16* __restrict__ srcs[4] = {
        Ahi + (size_t)m0 * 256, Alo + (size_t)m0 * 256,
        Bhi + (size_t)n0 * 256, Blo + (size_t)n0 * 256 };
#pragma unroll
    for (int arr = 0; arr < 4; arr++) {
        const __nv_bfloat16* __restrict__ s = srcs[arr];
#pragma unroll
        for (int c = 0; c < 4; c++) {
            const int idx = c * 256 + tid;
            const int row = idx >> 3;
            const int k16 = idx & 7;
            const uint32_t soff = (uint32_t)(row << 7) + (uint32_t)((k16 ^ (row & 7)) << 4);
            cp_async16(dst + arr * 16384 + soff,
                       s + (size_t)row * 256 + kc * 64 + k16 * 8);
        }
    }
    CP_COMMIT();
}

template<int MODE>
__global__ __launch_bounds__(256, 1)
void tc_gemm_kernel(const __nv_bfloat16* __restrict__ Ahi, const __nv_bfloat16* __restrict__ Alo,
                    const __nv_bfloat16* __restrict__ Bhi, const __nv_bfloat16* __restrict__ Blo,
                    const float* __restrict__ bias, float* __restrict__ C, int Ntot) {
    extern __shared__ char dsm[];
    const uint32_t sbase = smem_u32(dsm);

    const int tid = threadIdx.x;
    const int wid = tid >> 5;
    const int lane = tid & 31;
    const int n0 = blockIdx.x * 128;
    const int m0 = blockIdx.y * 128;
    const int wm = wid >> 1;
    const int wn = wid & 1;

    float acc[2][8][4];
#pragma unroll
    for (int mt = 0; mt < 2; mt++)
#pragma unroll
        for (int nt = 0; nt < 8; nt++)
#pragma unroll
            for (int e = 0; e < 4; e++) acc[mt][nt][e] = 0.f;

    load_stage(sbase, 0, Ahi, Alo, Bhi, Blo, m0, n0, 0, tid);

    const int q = lane >> 3;
    const int r = lane & 7;

    for (int kc = 0; kc < 4; kc++) {
        if (kc < 3) {
            load_stage(sbase, (kc + 1) & 1, Ahi, Alo, Bhi, Blo, m0, n0, kc + 1, tid);
            asm volatile("cp.async.wait_group 1;" ::: "memory");
        } else {
            asm volatile("cp.async.wait_group 0;" ::: "memory");
        }
        __syncthreads();

        const uint32_t st = sbase + (kc & 1) * STAGE_BYTES;
#pragma unroll
        for (int s = 0; s < 4; s++) {
            uint32_t aHi[2][4], aLo[2][4];
#pragma unroll
            for (int mt = 0; mt < 2; mt++) {
                const int arow = wm * 32 + mt * 16 + ((q & 1) << 3) + r;
                const int ac = 2 * s + (q >> 1);
                const uint32_t ad = st + (uint32_t)(arow << 7) + (uint32_t)((ac ^ (arow & 7)) << 4);
                LDSM_X4(aHi[mt][0], aHi[mt][1], aHi[mt][2], aHi[mt][3], ad);
                LDSM_X4(aLo[mt][0], aLo[mt][1], aLo[mt][2], aLo[mt][3], ad + 16384);
            }
            uint32_t bHi[8][2], bLo[8][2];
#pragma unroll
            for (int p = 0; p < 4; p++) {
                const int brow = wn * 64 + p * 16 + ((q >> 1) << 3) + r;
                const int bc = 2 * s + (q & 1);
                const uint32_t bd = st + 32768u + (uint32_t)(brow << 7) + (uint32_t)((bc ^ (brow & 7)) << 4);
                uint32_t t0, t1, t2, t3;
                LDSM_X4(t0, t1, t2, t3, bd);
                bHi[2 * p][0] = t0; bHi[2 * p][1] = t1;
                bHi[2 * p + 1][0] = t2; bHi[2 * p + 1][1] = t3;
                LDSM_X4(t0, t1, t2, t3, bd + 16384);
                bLo[2 * p][0] = t0; bLo[2 * p][1] = t1;
                bLo[2 * p + 1][0] = t2; bLo[2 * p + 1][1] = t3;
            }
#pragma unroll
            for (int mt = 0; mt < 2; mt++)
#pragma unroll
                for (int nt = 0; nt < 8; nt++) {
                    mma16816(acc[mt][nt], aHi[mt], bHi[nt]);
                    mma16816(acc[mt][nt], aHi[mt], bLo[nt]);
                    mma16816(acc[mt][nt], aLo[mt], bHi[nt]);
                }
        }
        __syncthreads();
    }

    const int r_base = m0 + wm * 32 + (lane >> 2);
    const int c_base = n0 + wn * 64 + (lane & 3) * 2;
    float2 bv[8];
#pragma unroll
    for (int nt = 0; nt < 8; nt++)
        bv[nt] = *reinterpret_cast<const float2*>(bias + c_base + nt * 8);

    if (MODE == 0) {
#pragma unroll
        for (int mt = 0; mt < 2; mt++) {
            const int rw = r_base + mt * 16;
#pragma unroll
            for (int nt = 0; nt < 8; nt++) {
                float2 v0, v1;
                v0.x = acc[mt][nt][0] + bv[nt].x;
                v0.y = acc[mt][nt][1] + bv[nt].y;
                v1.x = acc[mt][nt][2] + bv[nt].x;
                v1.y = acc[mt][nt][3] + bv[nt].y;
                *reinterpret_cast<float2*>(C + (size_t)rw * Ntot + c_base + nt * 8) = v0;
                *reinterpret_cast<float2*>(C + (size_t)(rw + 8) * Ntot + c_base + nt * 8) = v1;
            }
        }
    } else {
        const float bscale = (blockIdx.x < 2) ? 0.17677669529663687f : 1.0f;
#pragma unroll
        for (int mt = 0; mt < 2; mt++) {
            const int rw = r_base + mt * 16;
            const int b_ = rw >> 10;
            const int l0 = rw & 1023;
#pragma unroll
            for (int nt = 0; nt < 8; nt++) {
                const int gc = c_base + nt * 8;
                const int sec = gc >> 8;
                const int h_ = (gc >> 5) & 7;
                const int d_ = gc & 31;
                __half* dst = g_qkv16 + (size_t)((sec * BB + b_) * HH + h_) * (LSEQ * DHH) + d_;
                const float v0x = (acc[mt][nt][0] + bv[nt].x) * bscale;
                const float v0y = (acc[mt][nt][1] + bv[nt].y) * bscale;
                const float v1x = (acc[mt][nt][2] + bv[nt].x) * bscale;
                const float v1y = (acc[mt][nt][3] + bv[nt].y) * bscale;
                *reinterpret_cast<__half2*>(dst + (size_t)l0 * 32) = __floats2half2_rn(v0x, v0y);
                *reinterpret_cast<__half2*>(dst + (size_t)(l0 + 8) * 32) = __floats2half2_rn(v1x, v1y);
            }
        }
    }
}

// ---------------------------------------------------------------------------
// BANDED HMMA attention. One block per (b, h, image_row); 64 queries.
// Per query m16-tile mt, the valid keys fit a fixed 32-col window wb(mt):
// band = 7 halo rows x 32 cols = 224 keys (vs dense 448) -> acc 28 f32/thread
// -> 2 CTAs/SM (__launch_bounds__(512,2)).
// Warp = (mt = wid>>2, ws|nt = wid&3). QK^T B-frags via ldmatrix.x2 per
// (row n, col-group ws); PV B-frags via 32-row x4.trans per band chunk.
// Smem (bytes):
//   [0,40960)      Q 64x80 @0 ; K 448x80 @5120   (overlaid by P 64x448 @0)
//   [40960,76800)  V 448x80 (row-natural)
//   [76800,77824)  redM 64x4 f32
//   [77824,78848)  redS 64x4 f32
// ---------------------------------------------------------------------------
#define AT_SQ   0
#define AT_SK   5120
#define AT_SP   0
#define AT_SV   40960
#define AT_REDM 76800
#define AT_REDS 77824
#define AT_SMEM_BYTES 78848

__global__ __launch_bounds__(512, 2) void attn_kernel() {
    extern __shared__ char sm[];
    const uint32_t sb = smem_u32(sm);
    float* redM = reinterpret_cast<float*>(sm + AT_REDM);
    float* redS = reinterpret_cast<float*>(sm + AT_REDS);

    const int bid = blockIdx.x;          // b*128 + h*16 + rr
    const int rr = bid & 15;
    const int hh = (bid >> 4) & 7;
    const int b = bid >> 7;
    const int tid = threadIdx.x;

    const int rlo = max(0, rr - 3);
    const int rhi = min(IH - 1, rr + 3);
    const int nrows = rhi - rlo + 1;
    const int nk64 = nrows * 64;

    const __half* __restrict__ gq = g_qkv16 + (size_t)(b * HH + hh) * (LSEQ * DHH);
    const __half* __restrict__ gk = gq + QKV_SEC;
    const __half* __restrict__ gv = gk + QKV_SEC;

    // ---- Phase 1: pure cp.async. Group A: Q+K. Group B: V (overlaps QK^T).
    for (int e = tid; e < 64 * 4; e += 512) {
        const int row = e >> 2, ch = e & 3;
        cp_async16(sb + AT_SQ + row * 80 + ch * 16,
                   gq + (size_t)(rr * IW + row) * 32 + ch * 8);
    }
    for (int e = tid; e < nk64 * 4; e += 512) {
        const int row = e >> 2, ch = e & 3;
        cp_async16(sb + AT_SK + row * 80 + ch * 16,
                   gk + (size_t)(rlo * IW + row) * 32 + ch * 8);
    }
    CP_COMMIT();
    for (int e = tid; e < nk64 * 4; e += 512) {
        const int row = e >> 2, ch = e & 3;
        cp_async16(sb + AT_SV + row * 80 + ch * 16,
                   gv + (size_t)(rlo * IW + row) * 32 + ch * 8);
    }
    CP_COMMIT();
    // zero V pad rows (border blocks): P=0 there; avoid 0*garbage NaN
    for (int e = tid + nk64 * 4; e < 448 * 4; e += 512) {
        const int row = e >> 2, ch = e & 3;
        *reinterpret_cast<float4*>(sm + AT_SV + row * 80 + ch * 16) =
            make_float4(0.f, 0.f, 0.f, 0.f);
    }
    asm volatile("cp.async.wait_group 1;" ::: "memory");   // Q+K ready
    __syncthreads();

    const int wid = tid >> 5;
    const int lane = tid & 31;
    const int q = lane >> 3, r = lane & 7;
    const int mt = wid >> 2;
    const int ws = wid & 3;
    const int wb = min(max(mt * 16 - 8, 0), 32);     // band window start col
    const int qr = lane >> 2;

    // ================= banded QK^T =================
    float acc[7][4];
#pragma unroll
    for (int n = 0; n < 7; n++)
#pragma unroll
        for (int e = 0; e < 4; e++) acc[n][e] = 0.f;

#pragma unroll
    for (int s = 0; s < 2; s++) {
        uint32_t af[4];
        const int arow = mt * 16 + ((q & 1) << 3) + r;
        const int ac = 2 * s + (q >> 1);
        LDSM_X4(af[0], af[1], af[2], af[3], sb + AT_SQ + arow * 80 + ac * 16);
#pragma unroll
        for (int n = 0; n < 7; n++) {
            const int j0 = n * 64 + wb + 8 * ws;       // 8 consecutive keys
            uint32_t bb[2];
            LDSM_X2(bb[0], bb[1],
                    sb + AT_SK + (j0 + r) * 80 + (2 * s + (q & 1)) * 16);
            mma16816h(acc[n], af, bb);
        }
    }

    // ---- mask (window + halo-row validity; also kills garbage pad rows)
#pragma unroll
    for (int n = 0; n < 7; n++)
#pragma unroll
        for (int e = 0; e < 4; e++) {
            const int c = mt * 16 + qr + ((e >> 1) << 3);
            const int kcol = wb + 8 * ws + ((lane & 3) << 1) + (e & 1);
            const int dc = kcol - c;
            const bool valid = (n < nrows) && (dc >= -5) && (dc <= 5);
            if (!valid) acc[n][e] = -1e30f;
        }

    // ---- row max (4 warp-slices per row)
    float rmax[2];
#pragma unroll
    for (int h = 0; h < 2; h++) {
        float mv = -1e30f;
#pragma unroll
        for (int n = 0; n < 7; n++) {
            mv = fmaxf(mv, acc[n][2 * h]);
            mv = fmaxf(mv, acc[n][2 * h + 1]);
        }
        mv = fmaxf(mv, __shfl_xor_sync(0xffffffffu, mv, 1));
        mv = fmaxf(mv, __shfl_xor_sync(0xffffffffu, mv, 2));
        rmax[h] = mv;
    }
    if ((lane & 3) == 0) {
#pragma unroll
        for (int h = 0; h < 2; h++)
            redM[(mt * 16 + qr + 8 * h) * 4 + ws] = rmax[h];
    }
    __syncthreads();
    float gmax[2];
#pragma unroll
    for (int h = 0; h < 2; h++) {
        const float4 a4 = *reinterpret_cast<const float4*>(redM + (mt * 16 + qr + 8 * h) * 4);
        gmax[h] = fmaxf(fmaxf(a4.x, a4.y), fmaxf(a4.z, a4.w));
    }

    // ---- exp + row sum
    float rsum[2] = {0.f, 0.f};
#pragma unroll
    for (int n = 0; n < 7; n++)
#pragma unroll
        for (int e = 0; e < 4; e++) {
            const float ev = __expf(acc[n][e] - gmax[e >> 1]);
            acc[n][e] = ev;
            rsum[e >> 1] += ev;
        }
#pragma unroll
    for (int h = 0; h < 2; h++) {
        float sv = rsum[h];
        sv += __shfl_xor_sync(0xffffffffu, sv, 1);
        sv += __shfl_xor_sync(0xffffffffu, sv, 2);
        rsum[h] = sv;
    }
    if ((lane & 3) == 0) {
#pragma unroll
        for (int h = 0; h < 2; h++)
            redS[(mt * 16 + qr + 8 * h) * 4 + ws] = rsum[h];
    }
    __syncthreads();
    float ginv[2];
#pragma unroll
    for (int h = 0; h < 2; h++) {
        const float4 a4 = *reinterpret_cast<const float4*>(redS + (mt * 16 + qr + 8 * h) * 4);
        ginv[h] = 1.f / (a4.x + a4.y + a4.z + a4.w);
    }

    // ---- store P fp16 [64][224] (row stride 448B; overlays Q/K — all K/Q
    // reads are before the preceding __syncthreads())
#pragma unroll
    for (int n = 0; n < 7; n++) {
        const int kb = 32 * n + 8 * ws + ((lane & 3) << 1);
        const int row = mt * 16 + qr;
        *reinterpret_cast<__half2*>(sm + AT_SP + row * 448 + kb * 2) =
            __floats2half2_rn(acc[n][0] * ginv[0], acc[n][1] * ginv[0]);
        *reinterpret_cast<__half2*>(sm + AT_SP + (row + 8) * 448 + kb * 2) =
            __floats2half2_rn(acc[n][2] * ginv[1], acc[n][3] * ginv[1]);
    }
    asm volatile("cp.async.wait_group 0;" ::: "memory");   // V ready
    __syncthreads();

    // ================= banded PV =================
    // warp = (mt, nt): ctx[mt rows][nt*8 dims]; 14 k16 steps over 224 band keys
    const int nt = ws;
    float o[4] = {0.f, 0.f, 0.f, 0.f};
#pragma unroll
    for (int t = 0; t < 7; t++) {
        uint32_t bt[4];
        LDSM_X4_T(bt[0], bt[1], bt[2], bt[3],
                  sb + AT_SV + (t * 64 + wb + lane) * 80 + nt * 16);
#pragma unroll
        for (int ss = 0; ss < 2; ss++) {
            uint32_t af[4];
            const int arow = mt * 16 + ((q & 1) << 3) + r;
            const int ac = 2 * (2 * t + ss) + (q >> 1);
            LDSM_X4(af[0], af[1], af[2], af[3], sb + AT_SP + arow * 448 + ac * 16);
            mma16816h(o, af, bt + 2 * ss);
        }
    }

    // ---- epilogue: ctx -> bf16 hi/lo
    const int cq = mt * 16 + qr;
    const int d = nt * 8 + ((lane & 3) << 1);
    const size_t base = ((size_t)b * LSEQ + rr * IW) * EE + hh * DHH + d;
#pragma unroll
    for (int h = 0; h < 2; h++) {
        const size_t oi = base + (size_t)(cq + h * 8) * EE;
        const float v0 = o[h * 2], v1 = o[h * 2 + 1];
        __nv_bfloat16 h0 = __float2bfloat16(v0);
        __nv_bfloat16 h1 = __float2bfloat16(v1);
        __nv_bfloat162 hp; hp.x = h0; hp.y = h1;
        __nv_bfloat162 lp;
        lp.x = __float2bfloat16(v0 - __bfloat162float(h0));
        lp.y = __float2bfloat16(v1 - __bfloat162float(h1));
        *reinterpret_cast<__nv_bfloat162*>(g_ctx_hi + oi) = hp;
        *reinterpret_cast<__nv_bfloat162*>(g_ctx_lo + oi) = lp;
    }
}

// ---------------------------------------------------------------------------
extern "C" void kernel_launch(void* const* d_in, const int* in_sizes, int n_in,
                              void* d_out, int out_size) {
    const float* patch_embed = (const float*)d_in[0];  // [16,1024,256]
    const float* in_proj_w   = (const float*)d_in[1];  // [768,256]
    const float* in_proj_b   = (const float*)d_in[2];  // [768]
    const float* out_proj_w  = (const float*)d_in[3];  // [256,256]
    const float* out_proj_b  = (const float*)d_in[4];  // [256]
    const float* proj_w      = (const float*)d_in[5];  // [256,256]
    float* out = (float*)d_out;                        // [16,1024,256]

    static bool init_done = false;
    static void *p_xhi, *p_xlo, *p_wqhi, *p_wqlo, *p_wfhi, *p_wflo, *p_bf, *p_chi, *p_clo;
    if (!init_done) {
        cudaFuncSetAttribute(attn_kernel, cudaFuncAttributeMaxDynamicSharedMemorySize, AT_SMEM_BYTES);
        cudaFuncSetAttribute(tc_gemm_kernel<0>, cudaFuncAttributeMaxDynamicSharedMemorySize, GEMM_SMEM_BYTES);
        cudaFuncSetAttribute(tc_gemm_kernel<1>, cudaFuncAttributeMaxDynamicSharedMemorySize, GEMM_SMEM_BYTES);
        cudaGetSymbolAddress(&p_xhi,  g_x_hi);
        cudaGetSymbolAddress(&p_xlo,  g_x_lo);
        cudaGetSymbolAddress(&p_wqhi, g_wq_hi);
        cudaGetSymbolAddress(&p_wqlo, g_wq_lo);
        cudaGetSymbolAddress(&p_wfhi, g_wf_hi);
        cudaGetSymbolAddress(&p_wflo, g_wf_lo);
        cudaGetSymbolAddress(&p_bf,   g_bf);
        cudaGetSymbolAddress(&p_chi,  g_ctx_hi);
        cudaGetSymbolAddress(&p_clo,  g_ctx_lo);
        init_done = true;
    }

    // bf16 hi/lo splits of activations and qkv weights
    split_kernel<<<(M_ROWS * EE / 4 + 255) / 256, 256>>>(
        patch_embed, (__nv_bfloat16*)p_xhi, (__nv_bfloat16*)p_xlo, M_ROWS * EE / 4);
    split_kernel<<<(3 * EE * EE / 4 + 255) / 256, 256>>>(
        in_proj_w, (__nv_bfloat16*)p_wqhi, (__nv_bfloat16*)p_wqlo, 3 * EE * EE / 4);
    // fused output projection weights (hi/lo) + fused bias
    fuse_kernel<<<EE, 256>>>(proj_w, out_proj_w, out_proj_b);
    // QKV projection -> fp16 qkv in attention layout (q pre-scaled)
    tc_gemm_kernel<1><<<dim3(6, M_ROWS / 128), 256, GEMM_SMEM_BYTES>>>(
        (const __nv_bfloat16*)p_xhi, (const __nv_bfloat16*)p_xlo,
        (const __nv_bfloat16*)p_wqhi, (const __nv_bfloat16*)p_wqlo,
        in_proj_b, nullptr, 3 * EE);
    // banded HMMA local attention -> bf16 hi/lo ctx
    attn_kernel<<<BB * HH * IH, 512, AT_SMEM_BYTES>>>();
    // fused output projection straight into d_out
    tc_gemm_kernel<0><<<dim3(2, M_ROWS / 128), 256, GEMM_SMEM_BYTES>>>(
        (const __nv_bfloat16*)p_chi, (const __nv_bfloat16*)p_clo,
        (const __nv_bfloat16*)p_wfhi, (const __nv_bfloat16*)p_wflo,
        (const float*)p_bf, out, EE);
}